// round 9
// baseline (speedup 1.0000x reference)
#include <cuda_runtime.h>
#include <math.h>

#define VOCAB 10000

// ---------------- scratch (static device globals; no allocation) ----------------
static __device__ float    g_Gx[4096 * 1024];   // input-proj gates [row=b*64+t][1024]
static __device__ float    g_H[64 * 256];       // current hidden state [b][h]
static __device__ float    g_hsT[256 * 4096];   // hidden states TRANSPOSED [k][row]
static __device__ unsigned g_bar[512];          // per-(bg,step) barrier counters [bg*64+t]
static __device__ float    g_pmax[79 * 4096];   // softmax partial max   [tile][row]
static __device__ float    g_psum[79 * 4096];   // softmax partial sumexp[tile][row]
static __device__ float    g_lt[4096];          // target logit per row

__device__ __forceinline__ float sigm(float x) { return 1.0f / (1.0f + __expf(-x)); }

// FMA-pipe exp (no MUFU): exp(x) = 2^(x*log2e), deg-6 Taylor on f in [-.5,.5].
// Max rel err ~1.2e-7. Safe for any x (huge negatives clamp to ~2^-126 ~ 0).
__device__ __forceinline__ float fexp(float x)
{
    float y = x * 1.4426950408889634f;
    float n = rintf(y);
    float f = y - n;
    float p = 1.5403530e-4f;
    p = fmaf(p, f, 1.3333558e-3f);
    p = fmaf(p, f, 9.6181291e-3f);
    p = fmaf(p, f, 5.5504109e-2f);
    p = fmaf(p, f, 2.4022651e-1f);
    p = fmaf(p, f, 6.9314718e-1f);
    p = fmaf(p, f, 1.0f);
    int e = __float2int_rn(n);
    e = max(-126, min(127, e));
    return p * __int_as_float((e + 127) << 23);
}

__device__ __forceinline__ void cp16(unsigned dst, const void* src, int bytes)
{
    asm volatile("cp.async.cg.shared.global [%0], [%1], 16, %2;"
                 :: "r"(dst), "l"(src), "r"(bytes));
}

// ---------------- kA: embedding gather + X @ Wx + b -> g_Gx ----------------
// 128x128 tile, K=256, 8x8 micro. CTA(0,0) also zeroes the kB barrier counters.
__global__ void __launch_bounds__(256) kA(const int* __restrict__ idx,
                                          const float* __restrict__ E,
                                          const float* __restrict__ W,   // [512][1024]
                                          const float* __restrict__ bl)
{
    __shared__ __align__(16) float sm[4224];
    float* As = sm;            // [16][132] transposed: As[k][row]
    float* Bs = sm + 2112;     // [16][132]
    const int tid = threadIdx.x;
    const int tx = tid & 15, ty = tid >> 4;
    const int ro = blockIdx.y << 7;
    const int co = blockIdx.x << 7;

    if (blockIdx.x == 0 && blockIdx.y == 0) {
#pragma unroll
        for (int v = 0; v < 2; v++) g_bar[tid + (v << 8)] = 0u;
    }

    const int lrow = tid >> 1;
    const int lkb  = (tid & 1) << 3;
    const int erow = idx[ro + lrow];
    const int bk   = tid >> 4;
    const int bcb  = (tid & 15) << 3;

    float acc[8][8] = {};
    float4 na0, na1, nb0, nb1;

    {
        const float* sa = E + erow * 256 + lkb;
        na0 = *(const float4*)sa; na1 = *(const float4*)(sa + 4);
        const float* sb = W + bk * 1024 + co + bcb;
        nb0 = *(const float4*)sb; nb1 = *(const float4*)(sb + 4);
    }

    for (int kt = 0; kt < 16; kt++) {
        __syncthreads();
        {
            float* d = As + lrow;
            d[(lkb + 0) * 132] = na0.x; d[(lkb + 1) * 132] = na0.y;
            d[(lkb + 2) * 132] = na0.z; d[(lkb + 3) * 132] = na0.w;
            d[(lkb + 4) * 132] = na1.x; d[(lkb + 5) * 132] = na1.y;
            d[(lkb + 6) * 132] = na1.z; d[(lkb + 7) * 132] = na1.w;
            float* db = Bs + bk * 132 + bcb;
            *(float4*)db = nb0; *(float4*)(db + 4) = nb1;
        }
        __syncthreads();
        if (kt < 15) {
            int k0 = (kt + 1) << 4;
            const float* sa = E + erow * 256 + k0 + lkb;
            na0 = *(const float4*)sa; na1 = *(const float4*)(sa + 4);
            const float* sb = W + (k0 + bk) * 1024 + co + bcb;
            nb0 = *(const float4*)sb; nb1 = *(const float4*)(sb + 4);
        }
#pragma unroll
        for (int k = 0; k < 16; k++) {
            float4 a0 = *(const float4*)(As + k * 132 + (ty << 3));
            float4 a1 = *(const float4*)(As + k * 132 + (ty << 3) + 4);
            float4 b0 = *(const float4*)(Bs + k * 132 + (tx << 2));
            float4 b1 = *(const float4*)(Bs + k * 132 + 64 + (tx << 2));
            float a[8] = {a0.x, a0.y, a0.z, a0.w, a1.x, a1.y, a1.z, a1.w};
            float b[8] = {b0.x, b0.y, b0.z, b0.w, b1.x, b1.y, b1.z, b1.w};
#pragma unroll
            for (int i = 0; i < 8; i++)
#pragma unroll
                for (int j = 0; j < 8; j++)
                    acc[i][j] = fmaf(a[i], b[j], acc[i][j]);
        }
    }

    float bias[8];
#pragma unroll
    for (int j = 0; j < 8; j++) {
        int gc = co + ((j < 4) ? ((tx << 2) + j) : (64 + (tx << 2) + j - 4));
        bias[j] = bl[gc];
    }
#pragma unroll
    for (int i = 0; i < 8; i++) {
        int r = ro + (ty << 3) + i;
        float* dst0 = &g_Gx[r * 1024 + co + (tx << 2)];
        float4 v0 = {acc[i][0] + bias[0], acc[i][1] + bias[1],
                     acc[i][2] + bias[2], acc[i][3] + bias[3]};
        float4 v1 = {acc[i][4] + bias[4], acc[i][5] + bias[5],
                     acc[i][6] + bias[6], acc[i][7] + bias[7]};
        *(float4*)dst0 = v0;
        *(float4*)(dst0 + 64) = v1;
    }
}

// ---------------- kB: persistent LSTM recurrence (scalar FFMA) ----------------
// 128 CTAs = 8 batch-groups x 16 hid-groups. Warp = k-slice (kq = tid>>5).
// Per-BATCH-GROUP barrier (16 arrivals): consumers only need h from their own bg.
// t=0: h==0 so staging/GEMV skipped entirely (also removes g_H init).
__global__ void __launch_bounds__(256) kB(const float* __restrict__ W)   // W_lstm
{
    __shared__ __align__(16) float s_h[8 * 256];    // staged h [b][k]
    __shared__ __align__(16) float s_p[8 * 544];    // partials [kq][b*68 + lc]

    const int tid = threadIdx.x;
    const int bg = blockIdx.x >> 4;      // 0..7
    const int hg = blockIdx.x & 15;      // 0..15
    const int B0 = bg << 3;

    const int kq = tid >> 5;             // warp id = k slice (uniform per warp)
    const int cg = tid & 31;             // col pair
    const int lc0 = cg << 1;
    const int gc0 = ((lc0 >> 4) << 8) + (hg << 4) + (lc0 & 15);  // global gate col

    float w0[32], w1[32];
#pragma unroll
    for (int kk = 0; kk < 32; kk++) {
        const float* wr = W + (256 + (kq << 5) + kk) * 1024 + gc0;
        w0[kk] = wr[0];
        w1[kk] = wr[1];
    }

    const int rb = tid >> 4, rh = tid & 15;   // pointwise identity (tid<128)
    const int ghid = (hg << 4) + rh;
    float c_state = 0.0f;

    for (int t = 0; t < 64; t++) {
        if (t > 0) {
            // stage h[8 batches][256]: 512 float4 over 256 threads
#pragma unroll
            for (int v = 0; v < 2; v++) {
                int li = tid + (v << 8);
                int b = li >> 6, k4 = li & 63;
                ((float4*)s_h)[(b << 6) + k4] = ((const float4*)g_H)[((B0 + b) << 6) + k4];
            }
            __syncthreads();

#pragma unroll
            for (int b = 0; b < 8; b++) {
                const float4* hp = (const float4*)(s_h + (b << 8) + (kq << 5));
                float a0 = 0.0f, a1 = 0.0f;
#pragma unroll
                for (int q = 0; q < 8; q++) {
                    float4 h4 = hp[q];      // broadcast within warp
                    a0 = fmaf(h4.x, w0[4 * q + 0], a0); a1 = fmaf(h4.x, w1[4 * q + 0], a1);
                    a0 = fmaf(h4.y, w0[4 * q + 1], a0); a1 = fmaf(h4.y, w1[4 * q + 1], a1);
                    a0 = fmaf(h4.z, w0[4 * q + 2], a0); a1 = fmaf(h4.z, w1[4 * q + 2], a1);
                    a0 = fmaf(h4.w, w0[4 * q + 3], a0); a1 = fmaf(h4.w, w1[4 * q + 3], a1);
                }
                float2 pv = {a0, a1};
                *(float2*)(s_p + kq * 544 + b * 68 + lc0) = pv;   // conflict-free
            }
            __syncthreads();
        }

        if (tid < 128) {
            float sg[4] = {0.0f, 0.0f, 0.0f, 0.0f};
            if (t > 0) {
#pragma unroll
                for (int g = 0; g < 4; g++) {
                    float s = 0.0f;
#pragma unroll
                    for (int q = 0; q < 8; q++)
                        s += s_p[q * 544 + rb * 68 + (g << 4) + rh];
                    sg[g] = s;
                }
            }
            const float* gx = g_Gx + (((B0 + rb) << 6) + t) * 1024 + ghid;
            float vi = sg[0] + gx[0];
            float vj = sg[1] + gx[256];
            float vf = sg[2] + gx[512];
            float vo = sg[3] + gx[768];
            c_state = sigm(vf + 1.0f) * c_state + sigm(vi) * tanhf(vj);
            float h = sigm(vo) * tanhf(c_state);
            g_H[((B0 + rb) << 8) + ghid] = h;
            g_hsT[ghid * 4096 + ((B0 + rb) << 6) + t] = h;   // transposed for kC
        }

        if (t < 63) {   // per-bg barrier: 16 CTAs of this batch group
            __threadfence();
            __syncthreads();
            if (tid == 0) {
                unsigned* ctr = &g_bar[(bg << 6) + t];
                atomicAdd(ctr, 1u);
                volatile unsigned* p = ctr;
                while (*p < 16u) { }
                __threadfence();
            }
            __syncthreads();
        }
    }
}

// ---------------- kC: hsT^T @ W_dense + b, fused online-softmax partials ----------
// PERSISTENT (296 CTAs loop over 79x32 tiles). 128x128 tile, K=256, 8x8 scalar
// micro, 3-stage cp.async pipeline. exp via FMA-pipe poly (no MUFU).
__global__ void __launch_bounds__(256) kC(const float* __restrict__ Wd,
                                          const float* __restrict__ bd,
                                          const int* __restrict__ tgt)
{
    __shared__ __align__(16) float sm[12288];     // 3 x (As[16][128] + Bs[16][128])
    const int tid = threadIdx.x;
    const int tx = tid & 15, ty = tid >> 4;

    const int lk  = tid >> 5;            // loader k 0..7 (uniform per warp)
    const int lc4 = (tid & 31) << 2;     // loader col base 0..124

    const unsigned sbase = (unsigned)__cvta_generic_to_shared(sm);

    for (int tile = blockIdx.x; tile < 79 * 32; tile += gridDim.x) {
        const int bx = tile % 79;
        const int by = tile / 79;
        const int ro = by << 7;
        const int co = bx << 7;

        // issue one 16-k stage's cp.async loads into buffer buf
        auto issue = [&](int stage, int buf) {
            const unsigned Asb = sbase + buf * 16384u;        // bytes
            const unsigned Bsb = Asb + 8192u;
            const int k0 = stage << 4;
#pragma unroll
            for (int h = 0; h < 2; h++) {
                const int k = lk + (h << 3);
                cp16(Asb + (k << 9) + (lc4 << 2),
                     g_hsT + ((k0 + k) << 12) + ro + lc4, 16);
                const int gb = co + lc4;
                const int rem = VOCAB - gb;
                const int bytes = (rem >= 4) ? 16 : ((rem > 0) ? (rem << 2) : 0);
                const float* srcb = Wd + (k0 + k) * VOCAB + ((rem > 0) ? gb : 0);
                cp16(Bsb + (k << 9) + (lc4 << 2), srcb, bytes);
            }
        };

        float acc[8][8] = {};

        issue(0, 0);
        asm volatile("cp.async.commit_group;");
        issue(1, 1);
        asm volatile("cp.async.commit_group;");

        int bufc = 0;
        for (int i = 0; i < 16; i++) {
            if (i < 15) asm volatile("cp.async.wait_group 1;");
            else        asm volatile("cp.async.wait_group 0;");
            __syncthreads();

            const float* As = sm + bufc * 4096;
            const float* Bs = As + 2048;
#pragma unroll
            for (int k = 0; k < 16; k++) {
                float4 a0 = *(const float4*)(As + (k << 7) + (ty << 3));
                float4 a1 = *(const float4*)(As + (k << 7) + (ty << 3) + 4);
                float4 b0 = *(const float4*)(Bs + (k << 7) + (tx << 2));
                float4 b1 = *(const float4*)(Bs + (k << 7) + 64 + (tx << 2));
                float a[8] = {a0.x, a0.y, a0.z, a0.w, a1.x, a1.y, a1.z, a1.w};
                float b[8] = {b0.x, b0.y, b0.z, b0.w, b1.x, b1.y, b1.z, b1.w};
#pragma unroll
                for (int ii = 0; ii < 8; ii++)
#pragma unroll
                    for (int jj = 0; jj < 8; jj++)
                        acc[ii][jj] = fmaf(a[ii], b[jj], acc[ii][jj]);
            }

            if (i + 2 < 16) {
                int nb = bufc + 2; if (nb >= 3) nb -= 3;
                issue(i + 2, nb);
            }
            asm volatile("cp.async.commit_group;");
            if (++bufc == 3) bufc = 0;
        }

        // epilogue: bias, target-logit capture, per-thread row max/sumexp
        int   gcol[8];
        float bias[8];
        bool  valid[8];
#pragma unroll
        for (int j = 0; j < 8; j++) {
            int gc = co + ((j < 4) ? ((tx << 2) + j) : (64 + (tx << 2) + j - 4));
            gcol[j] = gc;
            valid[j] = (gc < VOCAB);
            bias[j] = valid[j] ? bd[gc] : 0.0f;
        }
        float m[8], s[8];
#pragma unroll
        for (int i = 0; i < 8; i++) {
            int gr = ro + (ty << 3) + i;
            int tg = tgt[gr];
            float mi = -1e30f;
#pragma unroll
            for (int j = 0; j < 8; j++) {
                float l = valid[j] ? (acc[i][j] + bias[j]) : -1e30f;
                acc[i][j] = l;
                if (valid[j] && gcol[j] == tg) g_lt[gr] = l;
                mi = fmaxf(mi, l);
            }
            float si = 0.0f;
#pragma unroll
            for (int j = 0; j < 8; j++) si += fexp(acc[i][j] - mi);
            m[i] = mi; s[i] = si;
        }

        __syncthreads();   // reuse smem for reduction
        float* redm = sm;          // [128][16]
        float* reds = sm + 2048;   // [128][16]
#pragma unroll
        for (int i = 0; i < 8; i++) {
            redm[((ty << 3) + i) * 16 + tx] = m[i];
            reds[((ty << 3) + i) * 16 + tx] = s[i];
        }
        __syncthreads();
        if (tid < 128) {
            float M = -1e30f;
#pragma unroll
            for (int x = 0; x < 16; x++) M = fmaxf(M, redm[tid * 16 + x]);
            float S = 0.0f;
#pragma unroll
            for (int x = 0; x < 16; x++) S += reds[tid * 16 + x] * fexp(redm[tid * 16 + x] - M);
            g_pmax[bx * 4096 + ro + tid] = M;
            g_psum[bx * 4096 + ro + tid] = S;
        }
        __syncthreads();   // protect smem before next tile's cp.async
    }
}

// ---------------- kD: combine partials -> perplexity ----------------
__global__ void kD(float* __restrict__ out)
{
    int r = blockIdx.x * 128 + threadIdx.x;   // = b*64 + t
    float M = g_pmax[r];
    float S = g_psum[r];
    for (int i = 1; i < 79; i++) {
        float mi = g_pmax[i * 4096 + r];
        float si = g_psum[i * 4096 + r];
        float nm = fmaxf(M, mi);
        S = S * fexp(M - nm) + si * fexp(mi - nm);
        M = nm;
    }
    out[r] = S * fexp(M - g_lt[r]);   // ppl = sumexp * exp(max - target_logit)
}

// ---------------- launch ----------------
extern "C" void kernel_launch(void* const* d_in, const int* in_sizes, int n_in,
                              void* d_out, int out_size)
{
    const int*   input_data = (const int*)d_in[0];
    const int*   targets    = (const int*)d_in[1];
    const float* E          = (const float*)d_in[2];
    const float* W_lstm     = (const float*)d_in[3];
    const float* b_lstm     = (const float*)d_in[4];
    const float* W_dense    = (const float*)d_in[5];
    const float* b_dense    = (const float*)d_in[6];
    float* out = (float*)d_out;
    (void)in_sizes; (void)n_in; (void)out_size;

    kA<<<dim3(8, 32), 256>>>(input_data, E, W_lstm, b_lstm);
    kB<<<128, 256>>>(W_lstm);
    kC<<<296, 256>>>(W_dense, b_dense, targets);
    kD<<<32, 128>>>(out);
}

// round 10
// speedup vs baseline: 1.0501x; 1.0501x over previous
#include <cuda_runtime.h>
#include <math.h>

#define VOCAB 10000

// ---------------- scratch (static device globals; no allocation) ----------------
static __device__ float    g_Gx[4096 * 1024];   // input-proj gates [row=b*64+t][1024]
static __device__ float    g_H[64 * 256];       // current hidden state [b][h]
static __device__ float    g_hsT[256 * 4096];   // hidden states TRANSPOSED [k][row]
static __device__ unsigned g_bar[512];          // per-(bg,step) barrier counters
static __device__ float    g_pmax[79 * 4096];   // softmax partial max   [tile][row]
static __device__ float    g_psum[79 * 4096];   // softmax partial sumexp[tile][row]
static __device__ float    g_lt[4096];          // target logit per row

__device__ __forceinline__ float sigm(float x) { return 1.0f / (1.0f + __expf(-x)); }

// FMA-pipe exp for x <= 0: exp(x) = 2^(x*log2e), deg-6 poly on f in [-.5,.5].
// Max rel err ~1.2e-7. Underflows cleanly to ~0 for huge negative x.
__device__ __forceinline__ float fexp(float x)
{
    float y = x * 1.4426950408889634f;
    float n = rintf(y);
    float f = y - n;
    float p = 1.5403530e-4f;
    p = fmaf(p, f, 1.3333558e-3f);
    p = fmaf(p, f, 9.6181291e-3f);
    p = fmaf(p, f, 5.5504109e-2f);
    p = fmaf(p, f, 2.4022651e-1f);
    p = fmaf(p, f, 6.9314718e-1f);
    p = fmaf(p, f, 1.0f);
    int e = __float2int_rn(n);
    e = max(e, -126);                 // inputs are <= 0, only clamp below
    return p * __int_as_float((e + 127) << 23);
}

__device__ __forceinline__ void cp16(unsigned dst, const void* src, int bytes)
{
    asm volatile("cp.async.cg.shared.global [%0], [%1], 16, %2;"
                 :: "r"(dst), "l"(src), "r"(bytes));
}

// ---------------- kA: embedding gather + X @ Wx + b -> g_Gx ----------------
// 128x128 tile, K=256, 8x8 micro. CTA(0,0) also zeroes the kB barrier counters.
__global__ void __launch_bounds__(256) kA(const int* __restrict__ idx,
                                          const float* __restrict__ E,
                                          const float* __restrict__ W,   // [512][1024]
                                          const float* __restrict__ bl)
{
    __shared__ __align__(16) float sm[4224];
    float* As = sm;            // [16][132] transposed: As[k][row]
    float* Bs = sm + 2112;     // [16][132]
    const int tid = threadIdx.x;
    const int tx = tid & 15, ty = tid >> 4;
    const int ro = blockIdx.y << 7;
    const int co = blockIdx.x << 7;

    if (blockIdx.x == 0 && blockIdx.y == 0) {
#pragma unroll
        for (int v = 0; v < 2; v++) g_bar[tid + (v << 8)] = 0u;
    }

    const int lrow = tid >> 1;
    const int lkb  = (tid & 1) << 3;
    const int erow = idx[ro + lrow];
    const int bk   = tid >> 4;
    const int bcb  = (tid & 15) << 3;

    float acc[8][8] = {};
    float4 na0, na1, nb0, nb1;

    {
        const float* sa = E + erow * 256 + lkb;
        na0 = *(const float4*)sa; na1 = *(const float4*)(sa + 4);
        const float* sb = W + bk * 1024 + co + bcb;
        nb0 = *(const float4*)sb; nb1 = *(const float4*)(sb + 4);
    }

    for (int kt = 0; kt < 16; kt++) {
        __syncthreads();
        {
            float* d = As + lrow;
            d[(lkb + 0) * 132] = na0.x; d[(lkb + 1) * 132] = na0.y;
            d[(lkb + 2) * 132] = na0.z; d[(lkb + 3) * 132] = na0.w;
            d[(lkb + 4) * 132] = na1.x; d[(lkb + 5) * 132] = na1.y;
            d[(lkb + 6) * 132] = na1.z; d[(lkb + 7) * 132] = na1.w;
            float* db = Bs + bk * 132 + bcb;
            *(float4*)db = nb0; *(float4*)(db + 4) = nb1;
        }
        __syncthreads();
        if (kt < 15) {
            int k0 = (kt + 1) << 4;
            const float* sa = E + erow * 256 + k0 + lkb;
            na0 = *(const float4*)sa; na1 = *(const float4*)(sa + 4);
            const float* sb = W + (k0 + bk) * 1024 + co + bcb;
            nb0 = *(const float4*)sb; nb1 = *(const float4*)(sb + 4);
        }
#pragma unroll
        for (int k = 0; k < 16; k++) {
            float4 a0 = *(const float4*)(As + k * 132 + (ty << 3));
            float4 a1 = *(const float4*)(As + k * 132 + (ty << 3) + 4);
            float4 b0 = *(const float4*)(Bs + k * 132 + (tx << 2));
            float4 b1 = *(const float4*)(Bs + k * 132 + 64 + (tx << 2));
            float a[8] = {a0.x, a0.y, a0.z, a0.w, a1.x, a1.y, a1.z, a1.w};
            float b[8] = {b0.x, b0.y, b0.z, b0.w, b1.x, b1.y, b1.z, b1.w};
#pragma unroll
            for (int i = 0; i < 8; i++)
#pragma unroll
                for (int j = 0; j < 8; j++)
                    acc[i][j] = fmaf(a[i], b[j], acc[i][j]);
        }
    }

    float bias[8];
#pragma unroll
    for (int j = 0; j < 8; j++) {
        int gc = co + ((j < 4) ? ((tx << 2) + j) : (64 + (tx << 2) + j - 4));
        bias[j] = bl[gc];
    }
#pragma unroll
    for (int i = 0; i < 8; i++) {
        int r = ro + (ty << 3) + i;
        float* dst0 = &g_Gx[r * 1024 + co + (tx << 2)];
        float4 v0 = {acc[i][0] + bias[0], acc[i][1] + bias[1],
                     acc[i][2] + bias[2], acc[i][3] + bias[3]};
        float4 v1 = {acc[i][4] + bias[4], acc[i][5] + bias[5],
                     acc[i][6] + bias[6], acc[i][7] + bias[7]};
        *(float4*)dst0 = v0;
        *(float4*)(dst0 + 64) = v1;
    }
}

// ---------------- kB: persistent LSTM recurrence (scalar FFMA) ----------------
// 128 CTAs = 8 batch-groups x 16 hid-groups. Warp = k-slice (kq = tid>>5).
// Per-BATCH-GROUP barrier (16 arrivals). t=0 staging/GEMV skipped (h0 == 0).
__global__ void __launch_bounds__(256) kB(const float* __restrict__ W)   // W_lstm
{
    __shared__ __align__(16) float s_h[8 * 256];    // staged h [b][k]
    __shared__ __align__(16) float s_p[8 * 544];    // partials [kq][b*68 + lc]

    const int tid = threadIdx.x;
    const int bg = blockIdx.x >> 4;      // 0..7
    const int hg = blockIdx.x & 15;      // 0..15
    const int B0 = bg << 3;

    const int kq = tid >> 5;             // warp id = k slice (uniform per warp)
    const int cg = tid & 31;             // col pair
    const int lc0 = cg << 1;
    const int gc0 = ((lc0 >> 4) << 8) + (hg << 4) + (lc0 & 15);  // global gate col

    float w0[32], w1[32];
#pragma unroll
    for (int kk = 0; kk < 32; kk++) {
        const float* wr = W + (256 + (kq << 5) + kk) * 1024 + gc0;
        w0[kk] = wr[0];
        w1[kk] = wr[1];
    }

    const int rb = tid >> 4, rh = tid & 15;   // pointwise identity (tid<128)
    const int ghid = (hg << 4) + rh;
    float c_state = 0.0f;

    for (int t = 0; t < 64; t++) {
        if (t > 0) {
#pragma unroll
            for (int v = 0; v < 2; v++) {
                int li = tid + (v << 8);
                int b = li >> 6, k4 = li & 63;
                ((float4*)s_h)[(b << 6) + k4] = ((const float4*)g_H)[((B0 + b) << 6) + k4];
            }
            __syncthreads();

#pragma unroll
            for (int b = 0; b < 8; b++) {
                const float4* hp = (const float4*)(s_h + (b << 8) + (kq << 5));
                float a0 = 0.0f, a1 = 0.0f;
#pragma unroll
                for (int q = 0; q < 8; q++) {
                    float4 h4 = hp[q];      // broadcast within warp
                    a0 = fmaf(h4.x, w0[4 * q + 0], a0); a1 = fmaf(h4.x, w1[4 * q + 0], a1);
                    a0 = fmaf(h4.y, w0[4 * q + 1], a0); a1 = fmaf(h4.y, w1[4 * q + 1], a1);
                    a0 = fmaf(h4.z, w0[4 * q + 2], a0); a1 = fmaf(h4.z, w1[4 * q + 2], a1);
                    a0 = fmaf(h4.w, w0[4 * q + 3], a0); a1 = fmaf(h4.w, w1[4 * q + 3], a1);
                }
                float2 pv = {a0, a1};
                *(float2*)(s_p + kq * 544 + b * 68 + lc0) = pv;   // conflict-free
            }
            __syncthreads();
        }

        if (tid < 128) {
            float sg[4] = {0.0f, 0.0f, 0.0f, 0.0f};
            if (t > 0) {
#pragma unroll
                for (int g = 0; g < 4; g++) {
                    float s = 0.0f;
#pragma unroll
                    for (int q = 0; q < 8; q++)
                        s += s_p[q * 544 + rb * 68 + (g << 4) + rh];
                    sg[g] = s;
                }
            }
            const float* gx = g_Gx + (((B0 + rb) << 6) + t) * 1024 + ghid;
            float vi = sg[0] + gx[0];
            float vj = sg[1] + gx[256];
            float vf = sg[2] + gx[512];
            float vo = sg[3] + gx[768];
            c_state = sigm(vf + 1.0f) * c_state + sigm(vi) * tanhf(vj);
            float h = sigm(vo) * tanhf(c_state);
            g_H[((B0 + rb) << 8) + ghid] = h;
            g_hsT[ghid * 4096 + ((B0 + rb) << 6) + t] = h;   // transposed for kC
        }

        if (t < 63) {   // per-bg barrier: 16 CTAs of this batch group
            __threadfence();
            __syncthreads();
            if (tid == 0) {
                unsigned* ctr = &g_bar[(bg << 6) + t];
                atomicAdd(ctr, 1u);
                volatile unsigned* p = ctr;
                while (*p < 16u) { }
                __threadfence();
            }
            __syncthreads();
        }
    }
}

// ---------------- kC: hsT^T @ W_dense + b, fused online-softmax partials ----------
// grid (79, 32). 128x128 tile, K=256, 8x8 scalar micro, 3-stage cp.async
// pipeline. exp via FMA-pipe poly (no MUFU contention with the GEMM).
__global__ void __launch_bounds__(256) kC(const float* __restrict__ Wd,
                                          const float* __restrict__ bd,
                                          const int* __restrict__ tgt)
{
    __shared__ __align__(16) float sm[12288];     // 3 x (As[16][128] + Bs[16][128])
    const int tid = threadIdx.x;
    const int tx = tid & 15, ty = tid >> 4;
    const int ro = blockIdx.y << 7;
    const int co = blockIdx.x << 7;

    const int lk  = tid >> 5;            // loader k 0..7 (uniform per warp)
    const int lc4 = (tid & 31) << 2;     // loader col base 0..124

    const unsigned sbase = (unsigned)__cvta_generic_to_shared(sm);

    auto issue = [&](int stage, int buf) {
        const unsigned Asb = sbase + buf * 16384u;
        const unsigned Bsb = Asb + 8192u;
        const int k0 = stage << 4;
#pragma unroll
        for (int h = 0; h < 2; h++) {
            const int k = lk + (h << 3);
            cp16(Asb + (k << 9) + (lc4 << 2),
                 g_hsT + ((k0 + k) << 12) + ro + lc4, 16);
            const int gb = co + lc4;
            const int rem = VOCAB - gb;
            const int bytes = (rem >= 4) ? 16 : ((rem > 0) ? (rem << 2) : 0);
            const float* srcb = Wd + (k0 + k) * VOCAB + ((rem > 0) ? gb : 0);
            cp16(Bsb + (k << 9) + (lc4 << 2), srcb, bytes);
        }
    };

    float acc[8][8] = {};

    issue(0, 0);
    asm volatile("cp.async.commit_group;");
    issue(1, 1);
    asm volatile("cp.async.commit_group;");

    int bufc = 0;
    for (int i = 0; i < 16; i++) {
        if (i < 15) asm volatile("cp.async.wait_group 1;");
        else        asm volatile("cp.async.wait_group 0;");
        __syncthreads();

        const float* As = sm + bufc * 4096;
        const float* Bs = As + 2048;
#pragma unroll
        for (int k = 0; k < 16; k++) {
            float4 a0 = *(const float4*)(As + (k << 7) + (ty << 3));
            float4 a1 = *(const float4*)(As + (k << 7) + (ty << 3) + 4);
            float4 b0 = *(const float4*)(Bs + (k << 7) + (tx << 2));
            float4 b1 = *(const float4*)(Bs + (k << 7) + 64 + (tx << 2));
            float a[8] = {a0.x, a0.y, a0.z, a0.w, a1.x, a1.y, a1.z, a1.w};
            float b[8] = {b0.x, b0.y, b0.z, b0.w, b1.x, b1.y, b1.z, b1.w};
#pragma unroll
            for (int ii = 0; ii < 8; ii++)
#pragma unroll
                for (int jj = 0; jj < 8; jj++)
                    acc[ii][jj] = fmaf(a[ii], b[jj], acc[ii][jj]);
        }

        if (i + 2 < 16) {
            int nb = bufc + 2; if (nb >= 3) nb -= 3;
            issue(i + 2, nb);
        }
        asm volatile("cp.async.commit_group;");
        if (++bufc == 3) bufc = 0;
    }

    // epilogue: bias, target-logit capture, per-thread row max/sumexp
    int   gcol[8];
    float bias[8];
    bool  valid[8];
#pragma unroll
    for (int j = 0; j < 8; j++) {
        int gc = co + ((j < 4) ? ((tx << 2) + j) : (64 + (tx << 2) + j - 4));
        gcol[j] = gc;
        valid[j] = (gc < VOCAB);
        bias[j] = valid[j] ? bd[gc] : 0.0f;
    }
    float m[8], s[8];
#pragma unroll
    for (int i = 0; i < 8; i++) {
        int gr = ro + (ty << 3) + i;
        int tg = tgt[gr];
        float mi = -1e30f;
#pragma unroll
        for (int j = 0; j < 8; j++) {
            float l = valid[j] ? (acc[i][j] + bias[j]) : -1e30f;
            acc[i][j] = l;
            if (valid[j] && gcol[j] == tg) g_lt[gr] = l;
            mi = fmaxf(mi, l);
        }
        float si = 0.0f;
#pragma unroll
        for (int j = 0; j < 8; j++) si += fexp(acc[i][j] - mi);
        m[i] = mi; s[i] = si;
    }

    __syncthreads();   // reuse smem for reduction
    float* redm = sm;          // [128][16]
    float* reds = sm + 2048;   // [128][16]
#pragma unroll
    for (int i = 0; i < 8; i++) {
        redm[((ty << 3) + i) * 16 + tx] = m[i];
        reds[((ty << 3) + i) * 16 + tx] = s[i];
    }
    __syncthreads();
    if (tid < 128) {
        float M = -1e30f;
#pragma unroll
        for (int x = 0; x < 16; x++) M = fmaxf(M, redm[tid * 16 + x]);
        float S = 0.0f;
#pragma unroll
        for (int x = 0; x < 16; x++) S += reds[tid * 16 + x] * fexp(redm[tid * 16 + x] - M);
        g_pmax[blockIdx.x * 4096 + ro + tid] = M;
        g_psum[blockIdx.x * 4096 + ro + tid] = S;
    }
}

// ---------------- kD: combine partials -> perplexity (warp per row) ----------------
__global__ void __launch_bounds__(256) kD(float* __restrict__ out)
{
    const int lane = threadIdx.x & 31;
    const int r = blockIdx.x * 8 + (threadIdx.x >> 5);   // row = b*64 + t

    float M = -1e30f, S = 0.0f;
    for (int i = lane; i < 79; i += 32) {
        float mi = g_pmax[i * 4096 + r];
        float si = g_psum[i * 4096 + r];
        float nm = fmaxf(M, mi);
        S = S * fexp(M - nm) + si * fexp(mi - nm);
        M = nm;
    }
#pragma unroll
    for (int d = 16; d > 0; d >>= 1) {
        float Mo = __shfl_xor_sync(0xFFFFFFFFu, M, d);
        float So = __shfl_xor_sync(0xFFFFFFFFu, S, d);
        float nm = fmaxf(M, Mo);
        S = S * fexp(M - nm) + So * fexp(Mo - nm);
        M = nm;
    }
    if (lane == 0)
        out[r] = S * fexp(M - g_lt[r]);   // ppl = sumexp * exp(max - target_logit)
}

// ---------------- launch ----------------
extern "C" void kernel_launch(void* const* d_in, const int* in_sizes, int n_in,
                              void* d_out, int out_size)
{
    const int*   input_data = (const int*)d_in[0];
    const int*   targets    = (const int*)d_in[1];
    const float* E          = (const float*)d_in[2];
    const float* W_lstm     = (const float*)d_in[3];
    const float* b_lstm     = (const float*)d_in[4];
    const float* W_dense    = (const float*)d_in[5];
    const float* b_dense    = (const float*)d_in[6];
    float* out = (float*)d_out;
    (void)in_sizes; (void)n_in; (void)out_size;

    kA<<<dim3(8, 32), 256>>>(input_data, E, W_lstm, b_lstm);
    kB<<<128, 256>>>(W_lstm);
    kC<<<dim3(79, 32), 256>>>(W_dense, b_dense, targets);
    kD<<<512, 256>>>(out);
}

// round 12
// speedup vs baseline: 1.0571x; 1.0066x over previous
#include <cuda_runtime.h>
#include <math.h>

#define VOCAB 10000

// ---------------- scratch (static device globals; no allocation) ----------------
static __device__ float    g_Gx[4096 * 1024];   // input-proj gates [row=b*64+t][1024]
static __device__ float    g_H[64 * 256];       // current hidden state [b][h]
static __device__ float    g_hsT[256 * 4096];   // hidden states TRANSPOSED [k][row]
static __device__ unsigned g_bar[512];          // per-(bg,step) barrier counters
static __device__ float    g_pmax[79 * 4096];   // softmax partial max   [tile][row]
static __device__ float    g_psum[79 * 4096];   // softmax partial sumexp[tile][row]
static __device__ float    g_lt[4096];          // target logit per row

__device__ __forceinline__ float sigm(float x) { return 1.0f / (1.0f + __expf(-x)); }

// FMA-pipe exp for x <= 0 (kD only — latency-bound there, no FMA-pipe contention)
__device__ __forceinline__ float fexp(float x)
{
    float y = x * 1.4426950408889634f;
    float n = rintf(y);
    float f = y - n;
    float p = 1.5403530e-4f;
    p = fmaf(p, f, 1.3333558e-3f);
    p = fmaf(p, f, 9.6181291e-3f);
    p = fmaf(p, f, 5.5504109e-2f);
    p = fmaf(p, f, 2.4022651e-1f);
    p = fmaf(p, f, 6.9314718e-1f);
    p = fmaf(p, f, 1.0f);
    int e = __float2int_rn(n);
    e = max(e, -126);
    return p * __int_as_float((e + 127) << 23);
}

__device__ __forceinline__ void cp16(unsigned dst, const void* src, int bytes)
{
    asm volatile("cp.async.cg.shared.global [%0], [%1], 16, %2;"
                 :: "r"(dst), "l"(src), "r"(bytes));
}

// ---------------- kA: embedding gather + X @ Wx + b -> g_Gx ----------------
// 128x128 tile, K=256, 8x8 micro. CTA(0,0) also zeroes the kB barrier counters.
__global__ void __launch_bounds__(256) kA(const int* __restrict__ idx,
                                          const float* __restrict__ E,
                                          const float* __restrict__ W,   // [512][1024]
                                          const float* __restrict__ bl)
{
    __shared__ __align__(16) float sm[4224];
    float* As = sm;            // [16][132] transposed: As[k][row]
    float* Bs = sm + 2112;     // [16][132]
    const int tid = threadIdx.x;
    const int tx = tid & 15, ty = tid >> 4;
    const int ro = blockIdx.y << 7;
    const int co = blockIdx.x << 7;

    if (blockIdx.x == 0 && blockIdx.y == 0) {
#pragma unroll
        for (int v = 0; v < 2; v++) g_bar[tid + (v << 8)] = 0u;
    }

    const int lrow = tid >> 1;
    const int lkb  = (tid & 1) << 3;
    const int erow = idx[ro + lrow];
    const int bk   = tid >> 4;
    const int bcb  = (tid & 15) << 3;

    float acc[8][8] = {};
    float4 na0, na1, nb0, nb1;

    {
        const float* sa = E + erow * 256 + lkb;
        na0 = *(const float4*)sa; na1 = *(const float4*)(sa + 4);
        const float* sb = W + bk * 1024 + co + bcb;
        nb0 = *(const float4*)sb; nb1 = *(const float4*)(sb + 4);
    }

    for (int kt = 0; kt < 16; kt++) {
        __syncthreads();
        {
            float* d = As + lrow;
            d[(lkb + 0) * 132] = na0.x; d[(lkb + 1) * 132] = na0.y;
            d[(lkb + 2) * 132] = na0.z; d[(lkb + 3) * 132] = na0.w;
            d[(lkb + 4) * 132] = na1.x; d[(lkb + 5) * 132] = na1.y;
            d[(lkb + 6) * 132] = na1.z; d[(lkb + 7) * 132] = na1.w;
            float* db = Bs + bk * 132 + bcb;
            *(float4*)db = nb0; *(float4*)(db + 4) = nb1;
        }
        __syncthreads();
        if (kt < 15) {
            int k0 = (kt + 1) << 4;
            const float* sa = E + erow * 256 + k0 + lkb;
            na0 = *(const float4*)sa; na1 = *(const float4*)(sa + 4);
            const float* sb = W + (k0 + bk) * 1024 + co + bcb;
            nb0 = *(const float4*)sb; nb1 = *(const float4*)(sb + 4);
        }
#pragma unroll
        for (int k = 0; k < 16; k++) {
            float4 a0 = *(const float4*)(As + k * 132 + (ty << 3));
            float4 a1 = *(const float4*)(As + k * 132 + (ty << 3) + 4);
            float4 b0 = *(const float4*)(Bs + k * 132 + (tx << 2));
            float4 b1 = *(const float4*)(Bs + k * 132 + 64 + (tx << 2));
            float a[8] = {a0.x, a0.y, a0.z, a0.w, a1.x, a1.y, a1.z, a1.w};
            float b[8] = {b0.x, b0.y, b0.z, b0.w, b1.x, b1.y, b1.z, b1.w};
#pragma unroll
            for (int i = 0; i < 8; i++)
#pragma unroll
                for (int j = 0; j < 8; j++)
                    acc[i][j] = fmaf(a[i], b[j], acc[i][j]);
        }
    }

    float bias[8];
#pragma unroll
    for (int j = 0; j < 8; j++) {
        int gc = co + ((j < 4) ? ((tx << 2) + j) : (64 + (tx << 2) + j - 4));
        bias[j] = bl[gc];
    }
#pragma unroll
    for (int i = 0; i < 8; i++) {
        int r = ro + (ty << 3) + i;
        float* dst0 = &g_Gx[r * 1024 + co + (tx << 2)];
        float4 v0 = {acc[i][0] + bias[0], acc[i][1] + bias[1],
                     acc[i][2] + bias[2], acc[i][3] + bias[3]};
        float4 v1 = {acc[i][4] + bias[4], acc[i][5] + bias[5],
                     acc[i][6] + bias[6], acc[i][7] + bias[7]};
        *(float4*)dst0 = v0;
        *(float4*)(dst0 + 64) = v1;
    }
}

// ---------------- kB: persistent LSTM recurrence (scalar FFMA) ----------------
// 128 CTAs = 8 batch-groups x 16 hid-groups. Warp = k-slice (kq = tid>>5).
// Per-BATCH-GROUP barrier (16 arrivals). t=0 staging/GEMV skipped (h0 == 0).
__global__ void __launch_bounds__(256) kB(const float* __restrict__ W)   // W_lstm
{
    __shared__ __align__(16) float s_h[8 * 256];    // staged h [b][k]
    __shared__ __align__(16) float s_p[8 * 544];    // partials [kq][b*68 + lc]

    const int tid = threadIdx.x;
    const int bg = blockIdx.x >> 4;      // 0..7
    const int hg = blockIdx.x & 15;      // 0..15
    const int B0 = bg << 3;

    const int kq = tid >> 5;             // warp id = k slice (uniform per warp)
    const int cg = tid & 31;             // col pair
    const int lc0 = cg << 1;
    const int gc0 = ((lc0 >> 4) << 8) + (hg << 4) + (lc0 & 15);  // global gate col

    float w0[32], w1[32];
#pragma unroll
    for (int kk = 0; kk < 32; kk++) {
        const float* wr = W + (256 + (kq << 5) + kk) * 1024 + gc0;
        w0[kk] = wr[0];
        w1[kk] = wr[1];
    }

    const int rb = tid >> 4, rh = tid & 15;   // pointwise identity (tid<128)
    const int ghid = (hg << 4) + rh;
    float c_state = 0.0f;

    for (int t = 0; t < 64; t++) {
        if (t > 0) {
#pragma unroll
            for (int v = 0; v < 2; v++) {
                int li = tid + (v << 8);
                int b = li >> 6, k4 = li & 63;
                ((float4*)s_h)[(b << 6) + k4] = ((const float4*)g_H)[((B0 + b) << 6) + k4];
            }
            __syncthreads();

#pragma unroll
            for (int b = 0; b < 8; b++) {
                const float4* hp = (const float4*)(s_h + (b << 8) + (kq << 5));
                float a0 = 0.0f, a1 = 0.0f;
#pragma unroll
                for (int q = 0; q < 8; q++) {
                    float4 h4 = hp[q];      // broadcast within warp
                    a0 = fmaf(h4.x, w0[4 * q + 0], a0); a1 = fmaf(h4.x, w1[4 * q + 0], a1);
                    a0 = fmaf(h4.y, w0[4 * q + 1], a0); a1 = fmaf(h4.y, w1[4 * q + 1], a1);
                    a0 = fmaf(h4.z, w0[4 * q + 2], a0); a1 = fmaf(h4.z, w1[4 * q + 2], a1);
                    a0 = fmaf(h4.w, w0[4 * q + 3], a0); a1 = fmaf(h4.w, w1[4 * q + 3], a1);
                }
                float2 pv = {a0, a1};
                *(float2*)(s_p + kq * 544 + b * 68 + lc0) = pv;   // conflict-free
            }
            __syncthreads();
        }

        if (tid < 128) {
            float sg[4] = {0.0f, 0.0f, 0.0f, 0.0f};
            if (t > 0) {
#pragma unroll
                for (int g = 0; g < 4; g++) {
                    float s = 0.0f;
#pragma unroll
                    for (int q = 0; q < 8; q++)
                        s += s_p[q * 544 + rb * 68 + (g << 4) + rh];
                    sg[g] = s;
                }
            }
            const float* gx = g_Gx + (((B0 + rb) << 6) + t) * 1024 + ghid;
            float vi = sg[0] + gx[0];
            float vj = sg[1] + gx[256];
            float vf = sg[2] + gx[512];
            float vo = sg[3] + gx[768];
            c_state = sigm(vf + 1.0f) * c_state + sigm(vi) * tanhf(vj);
            float h = sigm(vo) * tanhf(c_state);
            g_H[((B0 + rb) << 8) + ghid] = h;
            g_hsT[ghid * 4096 + ((B0 + rb) << 6) + t] = h;   // transposed for kC
        }

        if (t < 63) {   // per-bg barrier: 16 CTAs of this batch group
            __threadfence();
            __syncthreads();
            if (tid == 0) {
                unsigned* ctr = &g_bar[(bg << 6) + t];
                atomicAdd(ctr, 1u);
                volatile unsigned* p = ctr;
                while (*p < 16u) { }
                __threadfence();
            }
            __syncthreads();
        }
    }
}

// ---------------- kC: hsT^T @ W_dense + b, fused online-softmax partials ----------
// grid (79, 32). 128x128 tile, K=256, 8x8 scalar micro, 3-stage cp.async
// pipeline. Epilogue exp on MUFU (__expf) — overlaps with FMA pipe for free.
__global__ void __launch_bounds__(256) kC(const float* __restrict__ Wd,
                                          const float* __restrict__ bd,
                                          const int* __restrict__ tgt)
{
    __shared__ __align__(16) float sm[12288];     // 3 x (As[16][128] + Bs[16][128])
    const int tid = threadIdx.x;
    const int tx = tid & 15, ty = tid >> 4;
    const int ro = blockIdx.y << 7;
    const int co = blockIdx.x << 7;

    const int lk  = tid >> 5;            // loader k 0..7 (uniform per warp)
    const int lc4 = (tid & 31) << 2;     // loader col base 0..124

    const unsigned sbase = (unsigned)__cvta_generic_to_shared(sm);

    auto issue = [&](int stage, int buf) {
        const unsigned Asb = sbase + buf * 16384u;
        const unsigned Bsb = Asb + 8192u;
        const int k0 = stage << 4;
#pragma unroll
        for (int h = 0; h < 2; h++) {
            const int k = lk + (h << 3);
            cp16(Asb + (k << 9) + (lc4 << 2),
                 g_hsT + ((k0 + k) << 12) + ro + lc4, 16);
            const int gb = co + lc4;
            const int rem = VOCAB - gb;
            const int bytes = (rem >= 4) ? 16 : ((rem > 0) ? (rem << 2) : 0);
            const float* srcb = Wd + (k0 + k) * VOCAB + ((rem > 0) ? gb : 0);
            cp16(Bsb + (k << 9) + (lc4 << 2), srcb, bytes);
        }
    };

    float acc[8][8] = {};

    issue(0, 0);
    asm volatile("cp.async.commit_group;");
    issue(1, 1);
    asm volatile("cp.async.commit_group;");

    int bufc = 0;
    for (int i = 0; i < 16; i++) {
        if (i < 15) asm volatile("cp.async.wait_group 1;");
        else        asm volatile("cp.async.wait_group 0;");
        __syncthreads();

        const float* As = sm + bufc * 4096;
        const float* Bs = As + 2048;
#pragma unroll
        for (int k = 0; k < 16; k++) {
            float4 a0 = *(const float4*)(As + (k << 7) + (ty << 3));
            float4 a1 = *(const float4*)(As + (k << 7) + (ty << 3) + 4);
            float4 b0 = *(const float4*)(Bs + (k << 7) + (tx << 2));
            float4 b1 = *(const float4*)(Bs + (k << 7) + 64 + (tx << 2));
            float a[8] = {a0.x, a0.y, a0.z, a0.w, a1.x, a1.y, a1.z, a1.w};
            float b[8] = {b0.x, b0.y, b0.z, b0.w, b1.x, b1.y, b1.z, b1.w};
#pragma unroll
            for (int ii = 0; ii < 8; ii++)
#pragma unroll
                for (int jj = 0; jj < 8; jj++)
                    acc[ii][jj] = fmaf(a[ii], b[jj], acc[ii][jj]);
        }

        if (i + 2 < 16) {
            int nb = bufc + 2; if (nb >= 3) nb -= 3;
            issue(i + 2, nb);
        }
        asm volatile("cp.async.commit_group;");
        if (++bufc == 3) bufc = 0;
    }

    // epilogue: bias, target-logit capture, per-thread row max/sumexp
    int   gcol[8];
    float bias[8];
    bool  valid[8];
#pragma unroll
    for (int j = 0; j < 8; j++) {
        int gc = co + ((j < 4) ? ((tx << 2) + j) : (64 + (tx << 2) + j - 4));
        gcol[j] = gc;
        valid[j] = (gc < VOCAB);
        bias[j] = valid[j] ? bd[gc] : 0.0f;
    }
    float m[8], s[8];
#pragma unroll
    for (int i = 0; i < 8; i++) {
        int gr = ro + (ty << 3) + i;
        int tg = tgt[gr];
        float mi = -1e30f;
#pragma unroll
        for (int j = 0; j < 8; j++) {
            float l = valid[j] ? (acc[i][j] + bias[j]) : -1e30f;
            acc[i][j] = l;
            if (valid[j] && gcol[j] == tg) g_lt[gr] = l;
            mi = fmaxf(mi, l);
        }
        float si = 0.0f;
#pragma unroll
        for (int j = 0; j < 8; j++) si += __expf(acc[i][j] - mi);
        m[i] = mi; s[i] = si;
    }

    __syncthreads();   // reuse smem for reduction
    float* redm = sm;          // [128][16]
    float* reds = sm + 2048;   // [128][16]
#pragma unroll
    for (int i = 0; i < 8; i++) {
        redm[((ty << 3) + i) * 16 + tx] = m[i];
        reds[((ty << 3) + i) * 16 + tx] = s[i];
    }
    __syncthreads();
    if (tid < 128) {
        float M = -1e30f;
#pragma unroll
        for (int x = 0; x < 16; x++) M = fmaxf(M, redm[tid * 16 + x]);
        float S = 0.0f;
#pragma unroll
        for (int x = 0; x < 16; x++) S += reds[tid * 16 + x] * __expf(redm[tid * 16 + x] - M);
        g_pmax[blockIdx.x * 4096 + ro + tid] = M;
        g_psum[blockIdx.x * 4096 + ro + tid] = S;
    }
}

// ---------------- kD: combine partials -> perplexity (warp per row) ----------------
__global__ void __launch_bounds__(256) kD(float* __restrict__ out)
{
    const int lane = threadIdx.x & 31;
    const int r = blockIdx.x * 8 + (threadIdx.x >> 5);   // row = b*64 + t

    float M = -1e30f, S = 0.0f;
    for (int i = lane; i < 79; i += 32) {
        float mi = g_pmax[i * 4096 + r];
        float si = g_psum[i * 4096 + r];
        float nm = fmaxf(M, mi);
        S = S * fexp(M - nm) + si * fexp(mi - nm);
        M = nm;
    }
#pragma unroll
    for (int d = 16; d > 0; d >>= 1) {
        float Mo = __shfl_xor_sync(0xFFFFFFFFu, M, d);
        float So = __shfl_xor_sync(0xFFFFFFFFu, S, d);
        float nm = fmaxf(M, Mo);
        S = S * fexp(M - nm) + So * fexp(Mo - nm);
        M = nm;
    }
    if (lane == 0)
        out[r] = S * fexp(M - g_lt[r]);   // ppl = sumexp * exp(max - target_logit)
}

// ---------------- launch ----------------
extern "C" void kernel_launch(void* const* d_in, const int* in_sizes, int n_in,
                              void* d_out, int out_size)
{
    const int*   input_data = (const int*)d_in[0];
    const int*   targets    = (const int*)d_in[1];
    const float* E          = (const float*)d_in[2];
    const float* W_lstm     = (const float*)d_in[3];
    const float* b_lstm     = (const float*)d_in[4];
    const float* W_dense    = (const float*)d_in[5];
    const float* b_dense    = (const float*)d_in[6];
    float* out = (float*)d_out;
    (void)in_sizes; (void)n_in; (void)out_size;

    kA<<<dim3(8, 32), 256>>>(input_data, E, W_lstm, b_lstm);
    kB<<<128, 256>>>(W_lstm);
    kC<<<dim3(79, 32), 256>>>(W_dense, b_dense, targets);
    kD<<<512, 256>>>(out);
}

// round 13
// speedup vs baseline: 1.1357x; 1.0744x over previous
#include <cuda_runtime.h>
#include <math.h>

#define VOCAB 10000

// ---------------- scratch (static device globals; no allocation) ----------------
static __device__ float    g_Gx[4096 * 1024];   // input-proj gates [row=b*64+t][1024]
static __device__ float    g_H[64 * 256];       // current hidden state [b][h]
static __device__ float    g_hsT[256 * 4096];   // hidden states TRANSPOSED [k][row]
static __device__ unsigned g_bar[512];          // per-(bg,step) barrier counters
static __device__ float    g_pmax[79 * 4096];   // softmax partial max   [tile][row]
static __device__ float    g_psum[79 * 4096];   // softmax partial sumexp[tile][row]
static __device__ float    g_lt[4096];          // target logit per row

__device__ __forceinline__ float sigm(float x) { return 1.0f / (1.0f + __expf(-x)); }

// FMA-pipe exp for x <= 0 (kD only — latency-bound there, no FMA-pipe contention)
__device__ __forceinline__ float fexp(float x)
{
    float y = x * 1.4426950408889634f;
    float n = rintf(y);
    float f = y - n;
    float p = 1.5403530e-4f;
    p = fmaf(p, f, 1.3333558e-3f);
    p = fmaf(p, f, 9.6181291e-3f);
    p = fmaf(p, f, 5.5504109e-2f);
    p = fmaf(p, f, 2.4022651e-1f);
    p = fmaf(p, f, 6.9314718e-1f);
    p = fmaf(p, f, 1.0f);
    int e = __float2int_rn(n);
    e = max(e, -126);
    return p * __int_as_float((e + 127) << 23);
}

__device__ __forceinline__ void cp16(unsigned dst, const void* src, int bytes)
{
    asm volatile("cp.async.cg.shared.global [%0], [%1], 16, %2;"
                 :: "r"(dst), "l"(src), "r"(bytes));
}

// release-arrive / acquire-poll barrier primitives (no explicit membars)
__device__ __forceinline__ void bar_arrive(unsigned* ctr)
{
    asm volatile("red.release.gpu.global.add.u32 [%0], 1;" :: "l"(ctr) : "memory");
}
__device__ __forceinline__ unsigned bar_peek(const unsigned* ctr)
{
    unsigned v;
    asm volatile("ld.acquire.gpu.global.u32 %0, [%1];" : "=r"(v) : "l"(ctr) : "memory");
    return v;
}

// ---------------- kA: embedding gather + X @ Wx + b -> g_Gx ----------------
// 128x128 tile, K=256, 8x8 micro. CTA(0,0) also zeroes the kB barrier counters.
__global__ void __launch_bounds__(256) kA(const int* __restrict__ idx,
                                          const float* __restrict__ E,
                                          const float* __restrict__ W,   // [512][1024]
                                          const float* __restrict__ bl)
{
    __shared__ __align__(16) float sm[4224];
    float* As = sm;            // [16][132] transposed: As[k][row]
    float* Bs = sm + 2112;     // [16][132]
    const int tid = threadIdx.x;
    const int tx = tid & 15, ty = tid >> 4;
    const int ro = blockIdx.y << 7;
    const int co = blockIdx.x << 7;

    if (blockIdx.x == 0 && blockIdx.y == 0) {
#pragma unroll
        for (int v = 0; v < 2; v++) g_bar[tid + (v << 8)] = 0u;
    }

    const int lrow = tid >> 1;
    const int lkb  = (tid & 1) << 3;
    const int erow = idx[ro + lrow];
    const int bk   = tid >> 4;
    const int bcb  = (tid & 15) << 3;

    float acc[8][8] = {};
    float4 na0, na1, nb0, nb1;

    {
        const float* sa = E + erow * 256 + lkb;
        na0 = *(const float4*)sa; na1 = *(const float4*)(sa + 4);
        const float* sb = W + bk * 1024 + co + bcb;
        nb0 = *(const float4*)sb; nb1 = *(const float4*)(sb + 4);
    }

    for (int kt = 0; kt < 16; kt++) {
        __syncthreads();
        {
            float* d = As + lrow;
            d[(lkb + 0) * 132] = na0.x; d[(lkb + 1) * 132] = na0.y;
            d[(lkb + 2) * 132] = na0.z; d[(lkb + 3) * 132] = na0.w;
            d[(lkb + 4) * 132] = na1.x; d[(lkb + 5) * 132] = na1.y;
            d[(lkb + 6) * 132] = na1.z; d[(lkb + 7) * 132] = na1.w;
            float* db = Bs + bk * 132 + bcb;
            *(float4*)db = nb0; *(float4*)(db + 4) = nb1;
        }
        __syncthreads();
        if (kt < 15) {
            int k0 = (kt + 1) << 4;
            const float* sa = E + erow * 256 + k0 + lkb;
            na0 = *(const float4*)sa; na1 = *(const float4*)(sa + 4);
            const float* sb = W + (k0 + bk) * 1024 + co + bcb;
            nb0 = *(const float4*)sb; nb1 = *(const float4*)(sb + 4);
        }
#pragma unroll
        for (int k = 0; k < 16; k++) {
            float4 a0 = *(const float4*)(As + k * 132 + (ty << 3));
            float4 a1 = *(const float4*)(As + k * 132 + (ty << 3) + 4);
            float4 b0 = *(const float4*)(Bs + k * 132 + (tx << 2));
            float4 b1 = *(const float4*)(Bs + k * 132 + 64 + (tx << 2));
            float a[8] = {a0.x, a0.y, a0.z, a0.w, a1.x, a1.y, a1.z, a1.w};
            float b[8] = {b0.x, b0.y, b0.z, b0.w, b1.x, b1.y, b1.z, b1.w};
#pragma unroll
            for (int i = 0; i < 8; i++)
#pragma unroll
                for (int j = 0; j < 8; j++)
                    acc[i][j] = fmaf(a[i], b[j], acc[i][j]);
        }
    }

    float bias[8];
#pragma unroll
    for (int j = 0; j < 8; j++) {
        int gc = co + ((j < 4) ? ((tx << 2) + j) : (64 + (tx << 2) + j - 4));
        bias[j] = bl[gc];
    }
#pragma unroll
    for (int i = 0; i < 8; i++) {
        int r = ro + (ty << 3) + i;
        float* dst0 = &g_Gx[r * 1024 + co + (tx << 2)];
        float4 v0 = {acc[i][0] + bias[0], acc[i][1] + bias[1],
                     acc[i][2] + bias[2], acc[i][3] + bias[3]};
        float4 v1 = {acc[i][4] + bias[4], acc[i][5] + bias[5],
                     acc[i][6] + bias[6], acc[i][7] + bias[7]};
        *(float4*)dst0 = v0;
        *(float4*)(dst0 + 64) = v1;
    }
}

// ---------------- kB: persistent LSTM recurrence (scalar FFMA) ----------------
// 128 CTAs = 8 batch-groups x 16 hid-groups. Warp = k-slice (kq = tid>>5).
// Per-BATCH-GROUP barrier (16 arrivals) with release-arrive / acquire-poll
// (no explicit membars on the critical path). t=0 GEMV skipped (h0 == 0).
__global__ void __launch_bounds__(256) kB(const float* __restrict__ W)   // W_lstm
{
    __shared__ __align__(16) float s_h[8 * 256];    // staged h [b][k]
    __shared__ __align__(16) float s_p[8 * 544];    // partials [kq][b*68 + lc]

    const int tid = threadIdx.x;
    const int bg = blockIdx.x >> 4;      // 0..7
    const int hg = blockIdx.x & 15;      // 0..15
    const int B0 = bg << 3;

    const int kq = tid >> 5;             // warp id = k slice (uniform per warp)
    const int cg = tid & 31;             // col pair
    const int lc0 = cg << 1;
    const int gc0 = ((lc0 >> 4) << 8) + (hg << 4) + (lc0 & 15);  // global gate col

    float w0[32], w1[32];
#pragma unroll
    for (int kk = 0; kk < 32; kk++) {
        const float* wr = W + (256 + (kq << 5) + kk) * 1024 + gc0;
        w0[kk] = wr[0];
        w1[kk] = wr[1];
    }

    const int rb = tid >> 4, rh = tid & 15;   // pointwise identity (tid<128)
    const int ghid = (hg << 4) + rh;
    float c_state = 0.0f;

    for (int t = 0; t < 64; t++) {
        if (t > 0) {
#pragma unroll
            for (int v = 0; v < 2; v++) {
                int li = tid + (v << 8);
                int b = li >> 6, k4 = li & 63;
                ((float4*)s_h)[(b << 6) + k4] = ((const float4*)g_H)[((B0 + b) << 6) + k4];
            }
            __syncthreads();

#pragma unroll
            for (int b = 0; b < 8; b++) {
                const float4* hp = (const float4*)(s_h + (b << 8) + (kq << 5));
                float a0 = 0.0f, a1 = 0.0f;
#pragma unroll
                for (int q = 0; q < 8; q++) {
                    float4 h4 = hp[q];      // broadcast within warp
                    a0 = fmaf(h4.x, w0[4 * q + 0], a0); a1 = fmaf(h4.x, w1[4 * q + 0], a1);
                    a0 = fmaf(h4.y, w0[4 * q + 1], a0); a1 = fmaf(h4.y, w1[4 * q + 1], a1);
                    a0 = fmaf(h4.z, w0[4 * q + 2], a0); a1 = fmaf(h4.z, w1[4 * q + 2], a1);
                    a0 = fmaf(h4.w, w0[4 * q + 3], a0); a1 = fmaf(h4.w, w1[4 * q + 3], a1);
                }
                float2 pv = {a0, a1};
                *(float2*)(s_p + kq * 544 + b * 68 + lc0) = pv;   // conflict-free
            }
            __syncthreads();
        }

        if (tid < 128) {
            float sg[4] = {0.0f, 0.0f, 0.0f, 0.0f};
            if (t > 0) {
#pragma unroll
                for (int g = 0; g < 4; g++) {
                    float s = 0.0f;
#pragma unroll
                    for (int q = 0; q < 8; q++)
                        s += s_p[q * 544 + rb * 68 + (g << 4) + rh];
                    sg[g] = s;
                }
            }
            const float* gx = g_Gx + (((B0 + rb) << 6) + t) * 1024 + ghid;
            float vi = sg[0] + gx[0];
            float vj = sg[1] + gx[256];
            float vf = sg[2] + gx[512];
            float vo = sg[3] + gx[768];
            c_state = sigm(vf + 1.0f) * c_state + sigm(vi) * tanhf(vj);
            float h = sigm(vo) * tanhf(c_state);
            g_H[((B0 + rb) << 8) + ghid] = h;
            g_hsT[ghid * 4096 + ((B0 + rb) << 6) + t] = h;   // transposed for kC
        }

        if (t < 63) {   // per-bg barrier: 16 CTAs of this batch group
            __syncthreads();                       // all g_H stores issued
            if (tid == 0) {
                unsigned* ctr = &g_bar[(bg << 6) + t];
                bar_arrive(ctr);                   // release: orders prior stores
                while (bar_peek(ctr) < 16u) { }    // acquire: orders later loads
            }
            __syncthreads();
        }
    }
}

// ---------------- kC: hsT^T @ W_dense + b, fused online-softmax partials ----------
// grid (79, 32), 2 CTAs/SM (epilogue of one CTA overlaps mainloop of the other).
// 128x128 tile, K=256, 8x8 scalar micro, 3-stage cp.async pipeline, exp on MUFU.
__global__ void __launch_bounds__(256, 2) kC(const float* __restrict__ Wd,
                                             const float* __restrict__ bd,
                                             const int* __restrict__ tgt)
{
    __shared__ __align__(16) float sm[12288];     // 3 x (As[16][128] + Bs[16][128])
    const int tid = threadIdx.x;
    const int tx = tid & 15, ty = tid >> 4;
    const int ro = blockIdx.y << 7;
    const int co = blockIdx.x << 7;

    const int lk  = tid >> 5;            // loader k 0..7 (uniform per warp)
    const int lc4 = (tid & 31) << 2;     // loader col base 0..124

    const unsigned sbase = (unsigned)__cvta_generic_to_shared(sm);

    auto issue = [&](int stage, int buf) {
        const unsigned Asb = sbase + buf * 16384u;
        const unsigned Bsb = Asb + 8192u;
        const int k0 = stage << 4;
#pragma unroll
        for (int h = 0; h < 2; h++) {
            const int k = lk + (h << 3);
            cp16(Asb + (k << 9) + (lc4 << 2),
                 g_hsT + ((k0 + k) << 12) + ro + lc4, 16);
            const int gb = co + lc4;
            const int rem = VOCAB - gb;
            const int bytes = (rem >= 4) ? 16 : ((rem > 0) ? (rem << 2) : 0);
            const float* srcb = Wd + (k0 + k) * VOCAB + ((rem > 0) ? gb : 0);
            cp16(Bsb + (k << 9) + (lc4 << 2), srcb, bytes);
        }
    };

    float acc[8][8] = {};

    issue(0, 0);
    asm volatile("cp.async.commit_group;");
    issue(1, 1);
    asm volatile("cp.async.commit_group;");

    int bufc = 0;
    for (int i = 0; i < 16; i++) {
        if (i < 15) asm volatile("cp.async.wait_group 1;");
        else        asm volatile("cp.async.wait_group 0;");
        __syncthreads();

        const float* As = sm + bufc * 4096;
        const float* Bs = As + 2048;
#pragma unroll
        for (int k = 0; k < 16; k++) {
            float4 a0 = *(const float4*)(As + (k << 7) + (ty << 3));
            float4 a1 = *(const float4*)(As + (k << 7) + (ty << 3) + 4);
            float4 b0 = *(const float4*)(Bs + (k << 7) + (tx << 2));
            float4 b1 = *(const float4*)(Bs + (k << 7) + 64 + (tx << 2));
            float a[8] = {a0.x, a0.y, a0.z, a0.w, a1.x, a1.y, a1.z, a1.w};
            float b[8] = {b0.x, b0.y, b0.z, b0.w, b1.x, b1.y, b1.z, b1.w};
#pragma unroll
            for (int ii = 0; ii < 8; ii++)
#pragma unroll
                for (int jj = 0; jj < 8; jj++)
                    acc[ii][jj] = fmaf(a[ii], b[jj], acc[ii][jj]);
        }

        if (i + 2 < 16) {
            int nb = bufc + 2; if (nb >= 3) nb -= 3;
            issue(i + 2, nb);
        }
        asm volatile("cp.async.commit_group;");
        if (++bufc == 3) bufc = 0;
    }

    // epilogue: bias, target-logit capture, per-thread row max/sumexp
    int   gcol[8];
    float bias[8];
    bool  valid[8];
#pragma unroll
    for (int j = 0; j < 8; j++) {
        int gc = co + ((j < 4) ? ((tx << 2) + j) : (64 + (tx << 2) + j - 4));
        gcol[j] = gc;
        valid[j] = (gc < VOCAB);
        bias[j] = valid[j] ? bd[gc] : 0.0f;
    }
    float m[8], s[8];
#pragma unroll
    for (int i = 0; i < 8; i++) {
        int gr = ro + (ty << 3) + i;
        int tg = tgt[gr];
        float mi = -1e30f;
#pragma unroll
        for (int j = 0; j < 8; j++) {
            float l = valid[j] ? (acc[i][j] + bias[j]) : -1e30f;
            acc[i][j] = l;
            if (valid[j] && gcol[j] == tg) g_lt[gr] = l;
            mi = fmaxf(mi, l);
        }
        float si = 0.0f;
#pragma unroll
        for (int j = 0; j < 8; j++) si += __expf(acc[i][j] - mi);
        m[i] = mi; s[i] = si;
    }

    __syncthreads();   // reuse smem for reduction
    float* redm = sm;          // [128][16]
    float* reds = sm + 2048;   // [128][16]
#pragma unroll
    for (int i = 0; i < 8; i++) {
        redm[((ty << 3) + i) * 16 + tx] = m[i];
        reds[((ty << 3) + i) * 16 + tx] = s[i];
    }
    __syncthreads();
    if (tid < 128) {
        float M = -1e30f;
#pragma unroll
        for (int x = 0; x < 16; x++) M = fmaxf(M, redm[tid * 16 + x]);
        float S = 0.0f;
#pragma unroll
        for (int x = 0; x < 16; x++) S += reds[tid * 16 + x] * __expf(redm[tid * 16 + x] - M);
        g_pmax[blockIdx.x * 4096 + ro + tid] = M;
        g_psum[blockIdx.x * 4096 + ro + tid] = S;
    }
}

// ---------------- kD: combine partials -> perplexity (warp per row) ----------------
__global__ void __launch_bounds__(256) kD(float* __restrict__ out)
{
    const int lane = threadIdx.x & 31;
    const int r = blockIdx.x * 8 + (threadIdx.x >> 5);   // row = b*64 + t

    float M = -1e30f, S = 0.0f;
    for (int i = lane; i < 79; i += 32) {
        float mi = g_pmax[i * 4096 + r];
        float si = g_psum[i * 4096 + r];
        float nm = fmaxf(M, mi);
        S = S * fexp(M - nm) + si * fexp(mi - nm);
        M = nm;
    }
#pragma unroll
    for (int d = 16; d > 0; d >>= 1) {
        float Mo = __shfl_xor_sync(0xFFFFFFFFu, M, d);
        float So = __shfl_xor_sync(0xFFFFFFFFu, S, d);
        float nm = fmaxf(M, Mo);
        S = S * fexp(M - nm) + So * fexp(Mo - nm);
        M = nm;
    }
    if (lane == 0)
        out[r] = S * fexp(M - g_lt[r]);   // ppl = sumexp * exp(max - target_logit)
}

// ---------------- launch ----------------
extern "C" void kernel_launch(void* const* d_in, const int* in_sizes, int n_in,
                              void* d_out, int out_size)
{
    const int*   input_data = (const int*)d_in[0];
    const int*   targets    = (const int*)d_in[1];
    const float* E          = (const float*)d_in[2];
    const float* W_lstm     = (const float*)d_in[3];
    const float* b_lstm     = (const float*)d_in[4];
    const float* W_dense    = (const float*)d_in[5];
    const float* b_dense    = (const float*)d_in[6];
    float* out = (float*)d_out;
    (void)in_sizes; (void)n_in; (void)out_size;

    kA<<<dim3(8, 32), 256>>>(input_data, E, W_lstm, b_lstm);
    kB<<<128, 256>>>(W_lstm);
    kC<<<dim3(79, 32), 256>>>(W_dense, b_dense, targets);
    kD<<<512, 256>>>(out);
}

// round 14
// speedup vs baseline: 1.1591x; 1.0206x over previous
#include <cuda_runtime.h>
#include <math.h>

#define VOCAB 10000

// ---------------- scratch (static device globals; no allocation) ----------------
static __device__ float    g_Gx[4096 * 1024];   // input-proj gates [row=b*64+t][1024]
static __device__ float    g_H[64 * 256];       // current hidden state [b][h]
static __device__ float    g_hsT[256 * 4096];   // hidden states TRANSPOSED [k][row]
static __device__ unsigned g_bar[1024];         // per-(bg,step) barrier counters
static __device__ float    g_pmax[79 * 4096];   // softmax partial max   [tile][row]
static __device__ float    g_psum[79 * 4096];   // softmax partial sumexp[tile][row]
static __device__ float    g_lt[4096];          // target logit per row

__device__ __forceinline__ float sigm(float x) { return 1.0f / (1.0f + __expf(-x)); }

// fast exact-ish tanh via MUFU exp: rel err ~1e-7, saturates correctly
__device__ __forceinline__ float ftanh(float x)
{
    float ax = fabsf(x);
    float t = __expf(-2.0f * ax);
    float r = (1.0f - t) / (1.0f + t);
    return copysignf(r, x);
}

// FMA-pipe exp for x <= 0 (kD only — latency-bound there, no FMA-pipe contention)
__device__ __forceinline__ float fexp(float x)
{
    float y = x * 1.4426950408889634f;
    float n = rintf(y);
    float f = y - n;
    float p = 1.5403530e-4f;
    p = fmaf(p, f, 1.3333558e-3f);
    p = fmaf(p, f, 9.6181291e-3f);
    p = fmaf(p, f, 5.5504109e-2f);
    p = fmaf(p, f, 2.4022651e-1f);
    p = fmaf(p, f, 6.9314718e-1f);
    p = fmaf(p, f, 1.0f);
    int e = __float2int_rn(n);
    e = max(e, -126);
    return p * __int_as_float((e + 127) << 23);
}

__device__ __forceinline__ void cp16(unsigned dst, const void* src, int bytes)
{
    asm volatile("cp.async.cg.shared.global [%0], [%1], 16, %2;"
                 :: "r"(dst), "l"(src), "r"(bytes));
}

// release-arrive / acquire-poll barrier primitives (no explicit membars)
__device__ __forceinline__ void bar_arrive(unsigned* ctr)
{
    asm volatile("red.release.gpu.global.add.u32 [%0], 1;" :: "l"(ctr) : "memory");
}
__device__ __forceinline__ unsigned bar_peek(const unsigned* ctr)
{
    unsigned v;
    asm volatile("ld.acquire.gpu.global.u32 %0, [%1];" : "=r"(v) : "l"(ctr) : "memory");
    return v;
}

// ---------------- kA: embedding gather + X @ Wx + b -> g_Gx ----------------
// 128x128 tile, K=256, 8x8 micro. CTA(0,0) also zeroes the kB barrier counters.
__global__ void __launch_bounds__(256) kA(const int* __restrict__ idx,
                                          const float* __restrict__ E,
                                          const float* __restrict__ W,   // [512][1024]
                                          const float* __restrict__ bl)
{
    __shared__ __align__(16) float sm[4224];
    float* As = sm;            // [16][132] transposed: As[k][row]
    float* Bs = sm + 2112;     // [16][132]
    const int tid = threadIdx.x;
    const int tx = tid & 15, ty = tid >> 4;
    const int ro = blockIdx.y << 7;
    const int co = blockIdx.x << 7;

    if (blockIdx.x == 0 && blockIdx.y == 0) {
#pragma unroll
        for (int v = 0; v < 4; v++) g_bar[tid + (v << 8)] = 0u;
    }

    const int lrow = tid >> 1;
    const int lkb  = (tid & 1) << 3;
    const int erow = idx[ro + lrow];
    const int bk   = tid >> 4;
    const int bcb  = (tid & 15) << 3;

    float acc[8][8] = {};
    float4 na0, na1, nb0, nb1;

    {
        const float* sa = E + erow * 256 + lkb;
        na0 = *(const float4*)sa; na1 = *(const float4*)(sa + 4);
        const float* sb = W + bk * 1024 + co + bcb;
        nb0 = *(const float4*)sb; nb1 = *(const float4*)(sb + 4);
    }

    for (int kt = 0; kt < 16; kt++) {
        __syncthreads();
        {
            float* d = As + lrow;
            d[(lkb + 0) * 132] = na0.x; d[(lkb + 1) * 132] = na0.y;
            d[(lkb + 2) * 132] = na0.z; d[(lkb + 3) * 132] = na0.w;
            d[(lkb + 4) * 132] = na1.x; d[(lkb + 5) * 132] = na1.y;
            d[(lkb + 6) * 132] = na1.z; d[(lkb + 7) * 132] = na1.w;
            float* db = Bs + bk * 132 + bcb;
            *(float4*)db = nb0; *(float4*)(db + 4) = nb1;
        }
        __syncthreads();
        if (kt < 15) {
            int k0 = (kt + 1) << 4;
            const float* sa = E + erow * 256 + k0 + lkb;
            na0 = *(const float4*)sa; na1 = *(const float4*)(sa + 4);
            const float* sb = W + (k0 + bk) * 1024 + co + bcb;
            nb0 = *(const float4*)sb; nb1 = *(const float4*)(sb + 4);
        }
#pragma unroll
        for (int k = 0; k < 16; k++) {
            float4 a0 = *(const float4*)(As + k * 132 + (ty << 3));
            float4 a1 = *(const float4*)(As + k * 132 + (ty << 3) + 4);
            float4 b0 = *(const float4*)(Bs + k * 132 + (tx << 2));
            float4 b1 = *(const float4*)(Bs + k * 132 + 64 + (tx << 2));
            float a[8] = {a0.x, a0.y, a0.z, a0.w, a1.x, a1.y, a1.z, a1.w};
            float b[8] = {b0.x, b0.y, b0.z, b0.w, b1.x, b1.y, b1.z, b1.w};
#pragma unroll
            for (int i = 0; i < 8; i++)
#pragma unroll
                for (int j = 0; j < 8; j++)
                    acc[i][j] = fmaf(a[i], b[j], acc[i][j]);
        }
    }

    float bias[8];
#pragma unroll
    for (int j = 0; j < 8; j++) {
        int gc = co + ((j < 4) ? ((tx << 2) + j) : (64 + (tx << 2) + j - 4));
        bias[j] = bl[gc];
    }
#pragma unroll
    for (int i = 0; i < 8; i++) {
        int r = ro + (ty << 3) + i;
        float* dst0 = &g_Gx[r * 1024 + co + (tx << 2)];
        float4 v0 = {acc[i][0] + bias[0], acc[i][1] + bias[1],
                     acc[i][2] + bias[2], acc[i][3] + bias[3]};
        float4 v1 = {acc[i][4] + bias[4], acc[i][5] + bias[5],
                     acc[i][6] + bias[6], acc[i][7] + bias[7]};
        *(float4*)dst0 = v0;
        *(float4*)(dst0 + 64) = v1;
    }
}

// ---------------- kB: persistent LSTM recurrence (scalar FFMA) ----------------
// 256 CTAs = 16 batch-groups x 16 hid-groups (4 batches x 16 hids per CTA).
// Warp = k-slice (kq = tid>>5): s_h reads are bank-broadcasts. Per-BATCH-GROUP
// barrier (16 arrivals, release/acquire atomics). t=0 GEMV skipped (h0 == 0).
__global__ void __launch_bounds__(256) kB(const float* __restrict__ W)   // W_lstm
{
    __shared__ __align__(16) float s_h[4 * 256];    // staged h [b][k]
    __shared__ __align__(16) float s_p[8 * 272];    // partials [kq][b*68 + lc]

    const int tid = threadIdx.x;
    const int bg = blockIdx.x >> 4;      // 0..15
    const int hg = blockIdx.x & 15;      // 0..15
    const int B0 = bg << 2;

    const int kq = tid >> 5;             // warp id = k slice (uniform per warp)
    const int cg = tid & 31;             // col pair
    const int lc0 = cg << 1;
    const int gc0 = ((lc0 >> 4) << 8) + (hg << 4) + (lc0 & 15);  // global gate col

    float w0[32], w1[32];
#pragma unroll
    for (int kk = 0; kk < 32; kk++) {
        const float* wr = W + (256 + (kq << 5) + kk) * 1024 + gc0;
        w0[kk] = wr[0];
        w1[kk] = wr[1];
    }

    const int rb = tid >> 4, rh = tid & 15;   // pointwise identity (tid<64)
    const int ghid = (hg << 4) + rh;
    float c_state = 0.0f;

    for (int t = 0; t < 64; t++) {
        if (t > 0) {
            // stage h[4 batches][256]: 256 float4 over 256 threads
            {
                int b = tid >> 6, k4 = tid & 63;
                ((float4*)s_h)[(b << 6) + k4] = ((const float4*)g_H)[((B0 + b) << 6) + k4];
            }
            __syncthreads();

#pragma unroll
            for (int b = 0; b < 4; b++) {
                const float4* hp = (const float4*)(s_h + (b << 8) + (kq << 5));
                float a0 = 0.0f, a1 = 0.0f;
#pragma unroll
                for (int q = 0; q < 8; q++) {
                    float4 h4 = hp[q];      // broadcast within warp
                    a0 = fmaf(h4.x, w0[4 * q + 0], a0); a1 = fmaf(h4.x, w1[4 * q + 0], a1);
                    a0 = fmaf(h4.y, w0[4 * q + 1], a0); a1 = fmaf(h4.y, w1[4 * q + 1], a1);
                    a0 = fmaf(h4.z, w0[4 * q + 2], a0); a1 = fmaf(h4.z, w1[4 * q + 2], a1);
                    a0 = fmaf(h4.w, w0[4 * q + 3], a0); a1 = fmaf(h4.w, w1[4 * q + 3], a1);
                }
                float2 pv = {a0, a1};
                *(float2*)(s_p + kq * 272 + b * 68 + lc0) = pv;   // conflict-free
            }
            __syncthreads();
        }

        if (tid < 64) {
            float sg[4] = {0.0f, 0.0f, 0.0f, 0.0f};
            if (t > 0) {
#pragma unroll
                for (int g = 0; g < 4; g++) {
                    float s = 0.0f;
#pragma unroll
                    for (int q = 0; q < 8; q++)
                        s += s_p[q * 272 + rb * 68 + (g << 4) + rh];
                    sg[g] = s;
                }
            }
            const float* gx = g_Gx + (((B0 + rb) << 6) + t) * 1024 + ghid;
            float vi = sg[0] + gx[0];
            float vj = sg[1] + gx[256];
            float vf = sg[2] + gx[512];
            float vo = sg[3] + gx[768];
            c_state = sigm(vf + 1.0f) * c_state + sigm(vi) * ftanh(vj);
            float h = sigm(vo) * ftanh(c_state);
            g_H[((B0 + rb) << 8) + ghid] = h;
            g_hsT[ghid * 4096 + ((B0 + rb) << 6) + t] = h;   // transposed for kC
        }

        if (t < 63) {   // per-bg barrier: 16 CTAs of this batch group
            __syncthreads();                       // all g_H stores issued
            if (tid == 0) {
                unsigned* ctr = &g_bar[(bg << 6) + t];
                bar_arrive(ctr);                   // release: orders prior stores
                while (bar_peek(ctr) < 16u) { }    // acquire: orders later loads
            }
            __syncthreads();
        }
    }
}

// ---------------- kC: hsT^T @ W_dense + b, fused online-softmax partials ----------
// grid (79, 32), 2 CTAs/SM (epilogue of one CTA overlaps mainloop of the other).
// 128x128 tile, K=256, 8x8 scalar micro, 3-stage cp.async pipeline, exp on MUFU.
__global__ void __launch_bounds__(256, 2) kC(const float* __restrict__ Wd,
                                             const float* __restrict__ bd,
                                             const int* __restrict__ tgt)
{
    __shared__ __align__(16) float sm[12288];     // 3 x (As[16][128] + Bs[16][128])
    const int tid = threadIdx.x;
    const int tx = tid & 15, ty = tid >> 4;
    const int ro = blockIdx.y << 7;
    const int co = blockIdx.x << 7;

    const int lk  = tid >> 5;            // loader k 0..7 (uniform per warp)
    const int lc4 = (tid & 31) << 2;     // loader col base 0..124

    const unsigned sbase = (unsigned)__cvta_generic_to_shared(sm);

    auto issue = [&](int stage, int buf) {
        const unsigned Asb = sbase + buf * 16384u;
        const unsigned Bsb = Asb + 8192u;
        const int k0 = stage << 4;
#pragma unroll
        for (int h = 0; h < 2; h++) {
            const int k = lk + (h << 3);
            cp16(Asb + (k << 9) + (lc4 << 2),
                 g_hsT + ((k0 + k) << 12) + ro + lc4, 16);
            const int gb = co + lc4;
            const int rem = VOCAB - gb;
            const int bytes = (rem >= 4) ? 16 : ((rem > 0) ? (rem << 2) : 0);
            const float* srcb = Wd + (k0 + k) * VOCAB + ((rem > 0) ? gb : 0);
            cp16(Bsb + (k << 9) + (lc4 << 2), srcb, bytes);
        }
    };

    float acc[8][8] = {};

    issue(0, 0);
    asm volatile("cp.async.commit_group;");
    issue(1, 1);
    asm volatile("cp.async.commit_group;");

    int bufc = 0;
    for (int i = 0; i < 16; i++) {
        if (i < 15) asm volatile("cp.async.wait_group 1;");
        else        asm volatile("cp.async.wait_group 0;");
        __syncthreads();

        const float* As = sm + bufc * 4096;
        const float* Bs = As + 2048;
#pragma unroll
        for (int k = 0; k < 16; k++) {
            float4 a0 = *(const float4*)(As + (k << 7) + (ty << 3));
            float4 a1 = *(const float4*)(As + (k << 7) + (ty << 3) + 4);
            float4 b0 = *(const float4*)(Bs + (k << 7) + (tx << 2));
            float4 b1 = *(const float4*)(Bs + (k << 7) + 64 + (tx << 2));
            float a[8] = {a0.x, a0.y, a0.z, a0.w, a1.x, a1.y, a1.z, a1.w};
            float b[8] = {b0.x, b0.y, b0.z, b0.w, b1.x, b1.y, b1.z, b1.w};
#pragma unroll
            for (int ii = 0; ii < 8; ii++)
#pragma unroll
                for (int jj = 0; jj < 8; jj++)
                    acc[ii][jj] = fmaf(a[ii], b[jj], acc[ii][jj]);
        }

        if (i + 2 < 16) {
            int nb = bufc + 2; if (nb >= 3) nb -= 3;
            issue(i + 2, nb);
        }
        asm volatile("cp.async.commit_group;");
        if (++bufc == 3) bufc = 0;
    }

    // epilogue: bias, target-logit capture, per-thread row max/sumexp
    int   gcol[8];
    float bias[8];
    bool  valid[8];
#pragma unroll
    for (int j = 0; j < 8; j++) {
        int gc = co + ((j < 4) ? ((tx << 2) + j) : (64 + (tx << 2) + j - 4));
        gcol[j] = gc;
        valid[j] = (gc < VOCAB);
        bias[j] = valid[j] ? bd[gc] : 0.0f;
    }
    float m[8], s[8];
#pragma unroll
    for (int i = 0; i < 8; i++) {
        int gr = ro + (ty << 3) + i;
        int tg = tgt[gr];
        float mi = -1e30f;
#pragma unroll
        for (int j = 0; j < 8; j++) {
            float l = valid[j] ? (acc[i][j] + bias[j]) : -1e30f;
            acc[i][j] = l;
            if (valid[j] && gcol[j] == tg) g_lt[gr] = l;
            mi = fmaxf(mi, l);
        }
        float si = 0.0f;
#pragma unroll
        for (int j = 0; j < 8; j++) si += __expf(acc[i][j] - mi);
        m[i] = mi; s[i] = si;
    }

    __syncthreads();   // reuse smem for reduction
    float* redm = sm;          // [128][16]
    float* reds = sm + 2048;   // [128][16]
#pragma unroll
    for (int i = 0; i < 8; i++) {
        redm[((ty << 3) + i) * 16 + tx] = m[i];
        reds[((ty << 3) + i) * 16 + tx] = s[i];
    }
    __syncthreads();
    if (tid < 128) {
        float M = -1e30f;
#pragma unroll
        for (int x = 0; x < 16; x++) M = fmaxf(M, redm[tid * 16 + x]);
        float S = 0.0f;
#pragma unroll
        for (int x = 0; x < 16; x++) S += reds[tid * 16 + x] * __expf(redm[tid * 16 + x] - M);
        g_pmax[blockIdx.x * 4096 + ro + tid] = M;
        g_psum[blockIdx.x * 4096 + ro + tid] = S;
    }
}

// ---------------- kD: combine partials -> perplexity (warp per row) ----------------
__global__ void __launch_bounds__(256) kD(float* __restrict__ out)
{
    const int lane = threadIdx.x & 31;
    const int r = blockIdx.x * 8 + (threadIdx.x >> 5);   // row = b*64 + t

    float M = -1e30f, S = 0.0f;
    for (int i = lane; i < 79; i += 32) {
        float mi = g_pmax[i * 4096 + r];
        float si = g_psum[i * 4096 + r];
        float nm = fmaxf(M, mi);
        S = S * fexp(M - nm) + si * fexp(mi - nm);
        M = nm;
    }
#pragma unroll
    for (int d = 16; d > 0; d >>= 1) {
        float Mo = __shfl_xor_sync(0xFFFFFFFFu, M, d);
        float So = __shfl_xor_sync(0xFFFFFFFFu, S, d);
        float nm = fmaxf(M, Mo);
        S = S * fexp(M - nm) + So * fexp(Mo - nm);
        M = nm;
    }
    if (lane == 0)
        out[r] = S * fexp(M - g_lt[r]);   // ppl = sumexp * exp(max - target_logit)
}

// ---------------- launch ----------------
extern "C" void kernel_launch(void* const* d_in, const int* in_sizes, int n_in,
                              void* d_out, int out_size)
{
    const int*   input_data = (const int*)d_in[0];
    const int*   targets    = (const int*)d_in[1];
    const float* E          = (const float*)d_in[2];
    const float* W_lstm     = (const float*)d_in[3];
    const float* b_lstm     = (const float*)d_in[4];
    const float* W_dense    = (const float*)d_in[5];
    const float* b_dense    = (const float*)d_in[6];
    float* out = (float*)d_out;
    (void)in_sizes; (void)n_in; (void)out_size;

    kA<<<dim3(8, 32), 256>>>(input_data, E, W_lstm, b_lstm);
    kB<<<256, 256>>>(W_lstm);
    kC<<<dim3(79, 32), 256>>>(W_dense, b_dense, targets);
    kD<<<512, 256>>>(out);
}

// round 15
// speedup vs baseline: 1.2374x; 1.0676x over previous
#include <cuda_runtime.h>
#include <math.h>

#define VOCAB 10000

// ---------------- scratch (static device globals; no allocation) ----------------
static __device__ float    g_Gx[4096 * 1024];   // input-proj gates [row=b*64+t][1024]
static __device__ float    g_H[64 * 256];       // current hidden state [b][h]
static __device__ float    g_hsT[256 * 4096];   // hidden T-MAJOR: [k][row'=t*64+b]
static __device__ unsigned g_bar[512];          // per-(bg,step) barrier counters
static __device__ unsigned g_done[64];          // per-step completion (128 arrivals)
static __device__ unsigned g_tile;              // GEMM tile queue head
static __device__ float    g_pmax[79 * 4096];   // softmax partial max   [tile][row']
static __device__ float    g_psum[79 * 4096];   // softmax partial sumexp[tile][row']
static __device__ float    g_lt[4096];          // target logit per row'

__device__ __forceinline__ float sigm(float x) { return 1.0f / (1.0f + __expf(-x)); }

// fast tanh via MUFU exp: rel err ~1e-7
__device__ __forceinline__ float ftanh(float x)
{
    float ax = fabsf(x);
    float t = __expf(-2.0f * ax);
    float r = (1.0f - t) / (1.0f + t);
    return copysignf(r, x);
}

// FMA-pipe exp for x <= 0 (kD only)
__device__ __forceinline__ float fexp(float x)
{
    float y = x * 1.4426950408889634f;
    float n = rintf(y);
    float f = y - n;
    float p = 1.5403530e-4f;
    p = fmaf(p, f, 1.3333558e-3f);
    p = fmaf(p, f, 9.6181291e-3f);
    p = fmaf(p, f, 5.5504109e-2f);
    p = fmaf(p, f, 2.4022651e-1f);
    p = fmaf(p, f, 6.9314718e-1f);
    p = fmaf(p, f, 1.0f);
    int e = __float2int_rn(n);
    e = max(e, -126);
    return p * __int_as_float((e + 127) << 23);
}

__device__ __forceinline__ void cp16(unsigned dst, const void* src, int bytes)
{
    asm volatile("cp.async.cg.shared.global [%0], [%1], 16, %2;"
                 :: "r"(dst), "l"(src), "r"(bytes));
}

__device__ __forceinline__ void bar_arrive(unsigned* ctr)
{
    asm volatile("red.release.gpu.global.add.u32 [%0], 1;" :: "l"(ctr) : "memory");
}
__device__ __forceinline__ unsigned bar_peek(const unsigned* ctr)
{
    unsigned v;
    asm volatile("ld.acquire.gpu.global.u32 %0, [%1];" : "=r"(v) : "l"(ctr) : "memory");
    return v;
}

// ---------------- kA: embedding gather + X @ Wx + b -> g_Gx ----------------
// CTA(0,0) also zeroes all barrier/queue state for this launch.
__global__ void __launch_bounds__(256) kA(const int* __restrict__ idx,
                                          const float* __restrict__ E,
                                          const float* __restrict__ W,   // [512][1024]
                                          const float* __restrict__ bl)
{
    __shared__ __align__(16) float sm[4224];
    float* As = sm;            // [16][132] transposed: As[k][row]
    float* Bs = sm + 2112;     // [16][132]
    const int tid = threadIdx.x;
    const int tx = tid & 15, ty = tid >> 4;
    const int ro = blockIdx.y << 7;
    const int co = blockIdx.x << 7;

    if (blockIdx.x == 0 && blockIdx.y == 0) {
#pragma unroll
        for (int v = 0; v < 2; v++) g_bar[tid + (v << 8)] = 0u;
        if (tid < 64) g_done[tid] = 0u;
        if (tid == 0) g_tile = 0u;
    }

    const int lrow = tid >> 1;
    const int lkb  = (tid & 1) << 3;
    const int erow = idx[ro + lrow];
    const int bk   = tid >> 4;
    const int bcb  = (tid & 15) << 3;

    float acc[8][8] = {};
    float4 na0, na1, nb0, nb1;

    {
        const float* sa = E + erow * 256 + lkb;
        na0 = *(const float4*)sa; na1 = *(const float4*)(sa + 4);
        const float* sb = W + bk * 1024 + co + bcb;
        nb0 = *(const float4*)sb; nb1 = *(const float4*)(sb + 4);
    }

    for (int kt = 0; kt < 16; kt++) {
        __syncthreads();
        {
            float* d = As + lrow;
            d[(lkb + 0) * 132] = na0.x; d[(lkb + 1) * 132] = na0.y;
            d[(lkb + 2) * 132] = na0.z; d[(lkb + 3) * 132] = na0.w;
            d[(lkb + 4) * 132] = na1.x; d[(lkb + 5) * 132] = na1.y;
            d[(lkb + 6) * 132] = na1.z; d[(lkb + 7) * 132] = na1.w;
            float* db = Bs + bk * 132 + bcb;
            *(float4*)db = nb0; *(float4*)(db + 4) = nb1;
        }
        __syncthreads();
        if (kt < 15) {
            int k0 = (kt + 1) << 4;
            const float* sa = E + erow * 256 + k0 + lkb;
            na0 = *(const float4*)sa; na1 = *(const float4*)(sa + 4);
            const float* sb = W + (k0 + bk) * 1024 + co + bcb;
            nb0 = *(const float4*)sb; nb1 = *(const float4*)(sb + 4);
        }
#pragma unroll
        for (int k = 0; k < 16; k++) {
            float4 a0 = *(const float4*)(As + k * 132 + (ty << 3));
            float4 a1 = *(const float4*)(As + k * 132 + (ty << 3) + 4);
            float4 b0 = *(const float4*)(Bs + k * 132 + (tx << 2));
            float4 b1 = *(const float4*)(Bs + k * 132 + 64 + (tx << 2));
            float a[8] = {a0.x, a0.y, a0.z, a0.w, a1.x, a1.y, a1.z, a1.w};
            float b[8] = {b0.x, b0.y, b0.z, b0.w, b1.x, b1.y, b1.z, b1.w};
#pragma unroll
            for (int i = 0; i < 8; i++)
#pragma unroll
                for (int j = 0; j < 8; j++)
                    acc[i][j] = fmaf(a[i], b[j], acc[i][j]);
        }
    }

    float bias[8];
#pragma unroll
    for (int j = 0; j < 8; j++) {
        int gc = co + ((j < 4) ? ((tx << 2) + j) : (64 + (tx << 2) + j - 4));
        bias[j] = bl[gc];
    }
#pragma unroll
    for (int i = 0; i < 8; i++) {
        int r = ro + (ty << 3) + i;
        float* dst0 = &g_Gx[r * 1024 + co + (tx << 2)];
        float4 v0 = {acc[i][0] + bias[0], acc[i][1] + bias[1],
                     acc[i][2] + bias[2], acc[i][3] + bias[3]};
        float4 v1 = {acc[i][4] + bias[4], acc[i][5] + bias[5],
                     acc[i][6] + bias[6], acc[i][7] + bias[7]};
        *(float4*)dst0 = v0;
        *(float4*)(dst0 + 64) = v1;
    }
}

// ---------------- kF: fused LSTM (128 CTAs) + dense/softmax consumers ----------------
// 296 CTAs, 2/SM guaranteed. CTAs 0..127 run the recurrence and publish per-step
// completion in g_done[t]; all other CTAs (and LSTM CTAs once finished) pull
// 128x128 GEMM tiles from g_tile, polling g_done for their t-range.
__global__ void __launch_bounds__(256, 2) kF(const float* __restrict__ W,
                                             const float* __restrict__ Wd,
                                             const float* __restrict__ bd,
                                             const int* __restrict__ tgt)
{
    __shared__ __align__(16) float sm[12288];
    const int tid = threadIdx.x;

    if (blockIdx.x < 128) {
        // ---------------- LSTM role (R12 shape: 8 bg x 16 hg, 8 batches/CTA) --------
        float* s_h = sm;            // 2048 floats
        float* s_p = sm + 2048;     // 4352 floats

        const int bg = blockIdx.x >> 4;      // 0..7
        const int hg = blockIdx.x & 15;      // 0..15
        const int B0 = bg << 3;

        const int kq = tid >> 5;
        const int cg = tid & 31;
        const int lc0 = cg << 1;
        const int gc0 = ((lc0 >> 4) << 8) + (hg << 4) + (lc0 & 15);

        float w0[32], w1[32];
#pragma unroll
        for (int kk = 0; kk < 32; kk++) {
            const float* wr = W + (256 + (kq << 5) + kk) * 1024 + gc0;
            w0[kk] = wr[0];
            w1[kk] = wr[1];
        }

        const int rb = tid >> 4, rh = tid & 15;
        const int ghid = (hg << 4) + rh;
        float c_state = 0.0f;

        for (int t = 0; t < 64; t++) {
            if (t > 0) {
#pragma unroll
                for (int v = 0; v < 2; v++) {
                    int li = tid + (v << 8);
                    int b = li >> 6, k4 = li & 63;
                    ((float4*)s_h)[(b << 6) + k4] =
                        ((const float4*)g_H)[((B0 + b) << 6) + k4];
                }
                __syncthreads();

#pragma unroll
                for (int b = 0; b < 8; b++) {
                    const float4* hp = (const float4*)(s_h + (b << 8) + (kq << 5));
                    float a0 = 0.0f, a1 = 0.0f;
#pragma unroll
                    for (int q = 0; q < 8; q++) {
                        float4 h4 = hp[q];
                        a0 = fmaf(h4.x, w0[4*q+0], a0); a1 = fmaf(h4.x, w1[4*q+0], a1);
                        a0 = fmaf(h4.y, w0[4*q+1], a0); a1 = fmaf(h4.y, w1[4*q+1], a1);
                        a0 = fmaf(h4.z, w0[4*q+2], a0); a1 = fmaf(h4.z, w1[4*q+2], a1);
                        a0 = fmaf(h4.w, w0[4*q+3], a0); a1 = fmaf(h4.w, w1[4*q+3], a1);
                    }
                    float2 pv = {a0, a1};
                    *(float2*)(s_p + kq * 544 + b * 68 + lc0) = pv;
                }
                __syncthreads();
            }

            if (tid < 128) {
                float sg[4] = {0.0f, 0.0f, 0.0f, 0.0f};
                if (t > 0) {
#pragma unroll
                    for (int g = 0; g < 4; g++) {
                        float s = 0.0f;
#pragma unroll
                        for (int q = 0; q < 8; q++)
                            s += s_p[q * 544 + rb * 68 + (g << 4) + rh];
                        sg[g] = s;
                    }
                }
                const float* gx = g_Gx + (((B0 + rb) << 6) + t) * 1024 + ghid;
                float vi = sg[0] + gx[0];
                float vj = sg[1] + gx[256];
                float vf = sg[2] + gx[512];
                float vo = sg[3] + gx[768];
                c_state = sigm(vf + 1.0f) * c_state + sigm(vi) * ftanh(vj);
                float h = sigm(vo) * ftanh(c_state);
                g_H[((B0 + rb) << 8) + ghid] = h;
                g_hsT[ghid * 4096 + (t << 6) + (B0 + rb)] = h;   // T-MAJOR row'
            }

            __syncthreads();                       // all writes for step t issued
            if (tid == 0) {
                bar_arrive(&g_done[t]);            // publish step completion
                if (t < 63) {                      // per-bg barrier for recurrence
                    unsigned* ctr = &g_bar[(bg << 6) + t];
                    bar_arrive(ctr);
                    while (bar_peek(ctr) < 16u) { }
                }
            }
            if (t < 63) __syncthreads();
        }
    }

    // ---------------- GEMM consumer role (all CTAs end up here) ----------------
    const int tx = tid & 15, ty = tid >> 4;
    const int lk  = tid >> 5;
    const int lc4 = (tid & 31) << 2;
    const unsigned sbase = (unsigned)__cvta_generic_to_shared(sm);

    __shared__ unsigned s_tile;
    for (;;) {
        if (tid == 0) s_tile = atomicAdd(&g_tile, 1u);
        __syncthreads();
        const unsigned tile = s_tile;
        if (tile >= 79u * 32u) break;
        const int by = (int)(tile / 79u);
        const int bx = (int)(tile % 79u);
        const int ro = by << 7;               // row' = t*64+b; covers t in [2by, 2by+2)
        const int co = bx << 7;

        if (tid == 0) {
            const unsigned tneed = 2u * by + 1u;
            while (bar_peek(&g_done[tneed]) < 128u) { }
        }
        __syncthreads();                       // also fences smem reuse across tiles

        auto issue = [&](int stage, int buf) {
            const unsigned Asb = sbase + buf * 16384u;
            const unsigned Bsb = Asb + 8192u;
            const int k0 = stage << 4;
#pragma unroll
            for (int h = 0; h < 2; h++) {
                const int k = lk + (h << 3);
                cp16(Asb + (k << 9) + (lc4 << 2),
                     g_hsT + ((k0 + k) << 12) + ro + lc4, 16);
                const int gb = co + lc4;
                const int rem = VOCAB - gb;
                const int bytes = (rem >= 4) ? 16 : ((rem > 0) ? (rem << 2) : 0);
                const float* srcb = Wd + (k0 + k) * VOCAB + ((rem > 0) ? gb : 0);
                cp16(Bsb + (k << 9) + (lc4 << 2), srcb, bytes);
            }
        };

        float acc[8][8] = {};

        issue(0, 0);
        asm volatile("cp.async.commit_group;");
        issue(1, 1);
        asm volatile("cp.async.commit_group;");

        int bufc = 0;
        for (int i = 0; i < 16; i++) {
            if (i < 15) asm volatile("cp.async.wait_group 1;");
            else        asm volatile("cp.async.wait_group 0;");
            __syncthreads();

            const float* As = sm + bufc * 4096;
            const float* Bs = As + 2048;
#pragma unroll
            for (int k = 0; k < 16; k++) {
                float4 a0 = *(const float4*)(As + (k << 7) + (ty << 3));
                float4 a1 = *(const float4*)(As + (k << 7) + (ty << 3) + 4);
                float4 b0 = *(const float4*)(Bs + (k << 7) + (tx << 2));
                float4 b1 = *(const float4*)(Bs + (k << 7) + 64 + (tx << 2));
                float a[8] = {a0.x, a0.y, a0.z, a0.w, a1.x, a1.y, a1.z, a1.w};
                float b[8] = {b0.x, b0.y, b0.z, b0.w, b1.x, b1.y, b1.z, b1.w};
#pragma unroll
                for (int ii = 0; ii < 8; ii++)
#pragma unroll
                    for (int jj = 0; jj < 8; jj++)
                        acc[ii][jj] = fmaf(a[ii], b[jj], acc[ii][jj]);
            }

            if (i + 2 < 16) {
                int nb = bufc + 2; if (nb >= 3) nb -= 3;
                issue(i + 2, nb);
            }
            asm volatile("cp.async.commit_group;");
            if (++bufc == 3) bufc = 0;
        }

        // epilogue: bias, target-logit capture, per-thread row max/sumexp
        int   gcol[8];
        float bias[8];
        bool  valid[8];
#pragma unroll
        for (int j = 0; j < 8; j++) {
            int gc = co + ((j < 4) ? ((tx << 2) + j) : (64 + (tx << 2) + j - 4));
            gcol[j] = gc;
            valid[j] = (gc < VOCAB);
            bias[j] = valid[j] ? bd[gc] : 0.0f;
        }
        float m[8], s[8];
#pragma unroll
        for (int i = 0; i < 8; i++) {
            int gr = ro + (ty << 3) + i;                  // row'
            int rr = ((gr & 63) << 6) + (gr >> 6);        // b*64+t
            int tg = tgt[rr];
            float mi = -1e30f;
#pragma unroll
            for (int j = 0; j < 8; j++) {
                float l = valid[j] ? (acc[i][j] + bias[j]) : -1e30f;
                acc[i][j] = l;
                if (valid[j] && gcol[j] == tg) g_lt[gr] = l;
                mi = fmaxf(mi, l);
            }
            float si = 0.0f;
#pragma unroll
            for (int j = 0; j < 8; j++) si += __expf(acc[i][j] - mi);
            m[i] = mi; s[i] = si;
        }

        __syncthreads();   // reuse smem for reduction
        float* redm = sm;          // [128][16]
        float* reds = sm + 2048;   // [128][16]
#pragma unroll
        for (int i = 0; i < 8; i++) {
            redm[((ty << 3) + i) * 16 + tx] = m[i];
            reds[((ty << 3) + i) * 16 + tx] = s[i];
        }
        __syncthreads();
        if (tid < 128) {
            float M = -1e30f;
#pragma unroll
            for (int x = 0; x < 16; x++) M = fmaxf(M, redm[tid * 16 + x]);
            float S = 0.0f;
#pragma unroll
            for (int x = 0; x < 16; x++)
                S += reds[tid * 16 + x] * __expf(redm[tid * 16 + x] - M);
            g_pmax[bx * 4096 + ro + tid] = M;
            g_psum[bx * 4096 + ro + tid] = S;
        }
        __syncthreads();   // protect smem before next tile's cp.async
    }
}

// ---------------- kD: combine partials -> perplexity (warp per row') ----------------
__global__ void __launch_bounds__(256) kD(float* __restrict__ out)
{
    const int lane = threadIdx.x & 31;
    const int r = blockIdx.x * 8 + (threadIdx.x >> 5);   // row' = t*64 + b

    float M = -1e30f, S = 0.0f;
    for (int i = lane; i < 79; i += 32) {
        float mi = g_pmax[i * 4096 + r];
        float si = g_psum[i * 4096 + r];
        float nm = fmaxf(M, mi);
        S = S * fexp(M - nm) + si * fexp(mi - nm);
        M = nm;
    }
#pragma unroll
    for (int d = 16; d > 0; d >>= 1) {
        float Mo = __shfl_xor_sync(0xFFFFFFFFu, M, d);
        float So = __shfl_xor_sync(0xFFFFFFFFu, S, d);
        float nm = fmaxf(M, Mo);
        S = S * fexp(M - nm) + So * fexp(Mo - nm);
        M = nm;
    }
    if (lane == 0) {
        int rr = ((r & 63) << 6) + (r >> 6);   // b*64 + t
        out[rr] = S * fexp(M - g_lt[r]);
    }
}

// ---------------- launch ----------------
extern "C" void kernel_launch(void* const* d_in, const int* in_sizes, int n_in,
                              void* d_out, int out_size)
{
    const int*   input_data = (const int*)d_in[0];
    const int*   targets    = (const int*)d_in[1];
    const float* E          = (const float*)d_in[2];
    const float* W_lstm     = (const float*)d_in[3];
    const float* b_lstm     = (const float*)d_in[4];
    const float* W_dense    = (const float*)d_in[5];
    const float* b_dense    = (const float*)d_in[6];
    float* out = (float*)d_out;
    (void)in_sizes; (void)n_in; (void)out_size;

    kA<<<dim3(8, 32), 256>>>(input_data, E, W_lstm, b_lstm);
    kF<<<296, 256>>>(W_lstm, W_dense, b_dense, targets);
    kD<<<512, 256>>>(out);
}